// round 11
// baseline (speedup 1.0000x reference)
#include <cuda_runtime.h>
#include <cuda_bf16.h>
#include <math.h>
#include <stdint.h>

#define Bb   2
#define Ss   2048
#define Dd   2048
#define Hh   16
#define KVHh 4
#define HDd  128

typedef __nv_bfloat16 bf16;

// ---------------- scratch (static device globals; no allocs) ----------------
__device__ float g_q[Bb * Ss * Dd];            // fp32 q after proj
__device__ float g_k[Bb * Ss * KVHh * HDd];
__device__ float g_v[Bb * Ss * KVHh * HDd];
__device__ float g_cos[Ss * 64];
__device__ float g_sin[Ss * 64];
// split-bf16 operands. xh/xl: x-split -> Q-split (post) -> attn-out-split (flash)
__device__ __align__(16) bf16 g_xh[Bb * Ss * Dd];
__device__ __align__(16) bf16 g_xl[Bb * Ss * Dd];
__device__ __align__(16) bf16 g_wh[Dd * Dd];
__device__ __align__(16) bf16 g_wl[Dd * Dd];
__device__ __align__(16) bf16 g_kh[Bb * Ss * KVHh * HDd];
__device__ __align__(16) bf16 g_kl[Bb * Ss * KVHh * HDd];
__device__ __align__(16) bf16 g_vh[Bb * Ss * KVHh * HDd];
__device__ __align__(16) bf16 g_vl[Bb * Ss * KVHh * HDd];

// ---------------- helpers ----------------------------------------------------
__device__ __forceinline__ uint32_t smem_u32(const void* p) {
    uint32_t a;
    asm("{ .reg .u64 t; cvta.to.shared.u64 t, %1; cvt.u32.u64 %0, t; }" : "=r"(a) : "l"(p));
    return a;
}
#define CP_ASYNC16(dst, src) \
    asm volatile("cp.async.cg.shared.global [%0], [%1], 16;" :: "r"(dst), "l"(src) : "memory")
#define CP_COMMIT()  asm volatile("cp.async.commit_group;" ::: "memory")
#define CP_WAIT1()   asm volatile("cp.async.wait_group 1;" ::: "memory")
#define CP_WAIT0()   asm volatile("cp.async.wait_group 0;" ::: "memory")

__device__ __forceinline__ void mma16816(float* d, const uint32_t* a, const uint32_t* b) {
    asm volatile("mma.sync.aligned.m16n8k16.row.col.f32.bf16.bf16.f32 "
        "{%0,%1,%2,%3}, {%4,%5,%6,%7}, {%8,%9}, {%0,%1,%2,%3};"
        : "+f"(d[0]), "+f"(d[1]), "+f"(d[2]), "+f"(d[3])
        : "r"(a[0]), "r"(a[1]), "r"(a[2]), "r"(a[3]), "r"(b[0]), "r"(b[1]));
}
__device__ __forceinline__ void ldsm4(uint32_t* r, uint32_t a) {
    asm volatile("ldmatrix.sync.aligned.m8n8.x4.shared.b16 {%0,%1,%2,%3}, [%4];"
        : "=r"(r[0]), "=r"(r[1]), "=r"(r[2]), "=r"(r[3]) : "r"(a));
}
#define LDSM4T(r, a) \
    asm volatile("ldmatrix.sync.aligned.m8n8.x4.trans.shared.b16 {%0,%1,%2,%3}, [%4];" \
        : "=r"((r)[0]), "=r"((r)[1]), "=r"((r)[2]), "=r"((r)[3]) : "r"(a))

// pack two fp32 into bf16x2 (hi) and their residuals into bf16x2 (lo)
__device__ __forceinline__ void splitpk(float x0, float x1, uint32_t& hi, uint32_t& lo) {
    bf16 h0 = __float2bfloat16(x0), h1 = __float2bfloat16(x1);
    __nv_bfloat162 th = __halves2bfloat162(h0, h1);
    hi = *(uint32_t*)&th;
    bf16 r0 = __float2bfloat16(x0 - __bfloat162float(h0));
    bf16 r1 = __float2bfloat16(x1 - __bfloat162float(h1));
    __nv_bfloat162 tl = __halves2bfloat162(r0, r1);
    lo = *(uint32_t*)&tl;
}

// ---------------- RoPE table ------------------------------------------------
__global__ void rope_table_kernel() {
    int i = blockIdx.x * blockDim.x + threadIdx.x;
    if (i >= Ss * 64) return;
    int s = i >> 6, j = i & 63;
    float e   = (float)(2 * j) / (float)HDd;
    float inv = 1.0f / powf(10000.0f, e);
    float ang = (float)s * inv;
    g_cos[i] = (float)cos((double)ang);
    g_sin[i] = (float)sin((double)ang);
}

// ---------------- fp32 -> bf16 hi/lo split ----------------------------------
__global__ __launch_bounds__(256) void cvt_split(const float* __restrict__ src,
                                                 bf16* __restrict__ hi,
                                                 bf16* __restrict__ lo, int n4) {
    int i = blockIdx.x * blockDim.x + threadIdx.x;
    if (i >= n4) return;
    float4 v = ((const float4*)src)[i];
    uint32_t h0, l0, h1, l1;
    splitpk(v.x, v.y, h0, l0);
    splitpk(v.z, v.w, h1, l1);
    ((uint32_t*)hi)[2 * i] = h0; ((uint32_t*)hi)[2 * i + 1] = h1;
    ((uint32_t*)lo)[2 * i] = l0; ((uint32_t*)lo)[2 * i + 1] = l1;
}

// ---------------- split-bf16 HMMA GEMM: C = A @ B^T -------------------------
// A:[M,K], B:[N,K] row-major bf16 hi/lo. CTA tile 128x128, K-chunk 32,
// 8 warps 2(M)x4(N), warp tile 64x32. R8 pipeline; ldsm frags, 3 passes,
// NO forced occupancy bound (let ptxas pick regs; 2 CTAs fit if <=128).
#define LDA        40
#define ARRB       (128 * LDA * 2)          // 10240 B per operand array
#define STAGEB     (4 * ARRB)               // 40960 B per stage
#define GEMM_SMEM  (2 * STAGEB)             // 81920 B

__device__ __forceinline__ void gemm_load_chunk(
    uint32_t sm32, int buf, int tid, int c,
    const bf16* __restrict__ Ah, const bf16* __restrict__ Al,
    const bf16* __restrict__ Bh, const bf16* __restrict__ Bl,
    int bm, int bn, int K) {
    int row = tid >> 2;
    int t16 = tid & 3;
    uint32_t so = sm32 + buf * STAGEB + (uint32_t)row * 80 + (uint32_t)t16 * 16;
    size_t gA = (size_t)(bm + row) * K + (size_t)c * 32 + t16 * 8;
    size_t gB = (size_t)(bn + row) * K + (size_t)c * 32 + t16 * 8;
    size_t stp = (size_t)64 * K;
    CP_ASYNC16(so,                       Ah + gA);
    CP_ASYNC16(so + 64 * 80,             Ah + gA + stp);
    CP_ASYNC16(so + ARRB,                Al + gA);
    CP_ASYNC16(so + ARRB + 64 * 80,      Al + gA + stp);
    CP_ASYNC16(so + 2 * ARRB,            Bh + gB);
    CP_ASYNC16(so + 2 * ARRB + 64 * 80,  Bh + gB + stp);
    CP_ASYNC16(so + 3 * ARRB,            Bl + gB);
    CP_ASYNC16(so + 3 * ARRB + 64 * 80,  Bl + gB + stp);
}

__global__ __launch_bounds__(256) void gemm_bf16s(
    const bf16* __restrict__ Ah, const bf16* __restrict__ Al,
    const bf16* __restrict__ Bh, const bf16* __restrict__ Bl,
    float* __restrict__ C, int M, int N, int K) {
    extern __shared__ char sm[];
    const uint32_t sm32 = smem_u32(sm);
    const int tid  = threadIdx.x;
    const int wid  = tid >> 5, lane = tid & 31;
    const int lr   = lane >> 2, lc = lane & 3;
    const int lm   = lane & 15, lk2 = lane >> 4;
    const int wm   = wid & 1;
    const int wn   = wid >> 1;
    const int bm = blockIdx.y * 128, bn = blockIdx.x * 128;

    float acc[4][4][4];
#pragma unroll
    for (int i = 0; i < 4; i++)
#pragma unroll
        for (int j = 0; j < 4; j++)
#pragma unroll
            for (int r = 0; r < 4; r++) acc[i][j][r] = 0.0f;

    const int NC = K >> 5;
    gemm_load_chunk(sm32, 0, tid, 0, Ah, Al, Bh, Bl, bm, bn, K);
    CP_COMMIT();

    for (int c = 0; c < NC; c++) {
        const int buf = c & 1;
        if (c + 1 < NC) {
            gemm_load_chunk(sm32, buf ^ 1, tid, c + 1, Ah, Al, Bh, Bl, bm, bn, K);
            CP_COMMIT();
            CP_WAIT1();
        } else {
            CP_WAIT0();
        }
        __syncthreads();

        const uint32_t sbase = sm32 + buf * STAGEB;
        const uint32_t aad = sbase + (uint32_t)(wm * 64 + lm) * 80 + lk2 * 16;
        const uint32_t bad = sbase + 2 * ARRB + (uint32_t)(wn * 32 + lm) * 80 + lk2 * 16;
#pragma unroll
        for (int kst = 0; kst < 2; kst++) {
            const uint32_t ko = kst * 32;
            uint32_t ah[4][4], bh[2][4];
#pragma unroll
            for (int mt = 0; mt < 4; mt++) ldsm4(ah[mt], aad + mt * 1280 + ko);
#pragma unroll
            for (int p = 0; p < 2; p++)    ldsm4(bh[p], bad + p * 1280 + ko);
            // pass 1: Ah*Bh
#pragma unroll
            for (int mt = 0; mt < 4; mt++)
#pragma unroll
                for (int nt = 0; nt < 4; nt++) {
                    uint32_t bf[2] = { bh[nt >> 1][nt & 1], bh[nt >> 1][(nt & 1) + 2] };
                    mma16816(acc[mt][nt], ah[mt], bf);
                }
            // pass 2: Al*Bh (reuse bh; al loaded fresh)
            {
                uint32_t al[4][4];
#pragma unroll
                for (int mt = 0; mt < 4; mt++) ldsm4(al[mt], aad + ARRB + mt * 1280 + ko);
#pragma unroll
                for (int mt = 0; mt < 4; mt++)
#pragma unroll
                    for (int nt = 0; nt < 4; nt++) {
                        uint32_t bf[2] = { bh[nt >> 1][nt & 1], bh[nt >> 1][(nt & 1) + 2] };
                        mma16816(acc[mt][nt], al[mt], bf);
                    }
            }
            // pass 3: Ah*Bl (al dead; bl loaded into bh's slot scope)
            {
                uint32_t bl[2][4];
#pragma unroll
                for (int p = 0; p < 2; p++) ldsm4(bl[p], bad + ARRB + p * 1280 + ko);
#pragma unroll
                for (int mt = 0; mt < 4; mt++)
#pragma unroll
                    for (int nt = 0; nt < 4; nt++) {
                        uint32_t bf[2] = { bl[nt >> 1][nt & 1], bl[nt >> 1][(nt & 1) + 2] };
                        mma16816(acc[mt][nt], ah[mt], bf);
                    }
            }
        }
        __syncthreads();
    }

#pragma unroll
    for (int mt = 0; mt < 4; mt++) {
        int m = bm + wm * 64 + mt * 16 + lr;
#pragma unroll
        for (int nt = 0; nt < 4; nt++) {
            int n = bn + wn * 32 + nt * 8 + lc * 2;
            *(float2*)(C + (size_t)m * N + n)       = make_float2(acc[mt][nt][0], acc[mt][nt][1]);
            *(float2*)(C + (size_t)(m + 8) * N + n) = make_float2(acc[mt][nt][2], acc[mt][nt][3]);
        }
    }
}

// ---------------- q/k epilogues: RMSNorm + RoPE (+gain) -> bf16 hi/lo -------
__global__ __launch_bounds__(256) void q_post(const float* __restrict__ gain,
                                              bf16* __restrict__ qh, bf16* __restrict__ ql) {
    int wid  = blockIdx.x * 8 + (threadIdx.x >> 5);
    int lane = threadIdx.x & 31;
    int h = wid & (Hh - 1);
    int s = (wid >> 4) & (Ss - 1);
    const float* base = g_q + (size_t)wid * 128;
    float e0 = base[lane], e1 = base[lane + 32], e2 = base[lane + 64], e3 = base[lane + 96];
    float ssum = e0 * e0 + e1 * e1 + e2 * e2 + e3 * e3;
#pragma unroll
    for (int o = 16; o > 0; o >>= 1) ssum += __shfl_xor_sync(0xffffffffu, ssum, o);
    float r = rsqrtf(ssum * (1.0f / 128.0f) + 1e-6f);
    float g = gain[h] * r * 0.08838834764831845f;
    float c0 = g_cos[s * 64 + lane],      sn0 = g_sin[s * 64 + lane];
    float c1 = g_cos[s * 64 + lane + 32], sn1 = g_sin[s * 64 + lane + 32];
    float o0 = ( e0 * c0  + e2 * sn0) * g;
    float o1 = ( e1 * c1  + e3 * sn1) * g;
    float o2 = (-e0 * sn0 + e2 * c0 ) * g;
    float o3 = (-e1 * sn1 + e3 * c1 ) * g;
    size_t off = (size_t)wid * 128;
    bf16 h0 = __float2bfloat16(o0); qh[off + lane]      = h0; ql[off + lane]      = __float2bfloat16(o0 - __bfloat162float(h0));
    bf16 h1 = __float2bfloat16(o1); qh[off + lane + 32] = h1; ql[off + lane + 32] = __float2bfloat16(o1 - __bfloat162float(h1));
    bf16 h2 = __float2bfloat16(o2); qh[off + lane + 64] = h2; ql[off + lane + 64] = __float2bfloat16(o2 - __bfloat162float(h2));
    bf16 h3 = __float2bfloat16(o3); qh[off + lane + 96] = h3; ql[off + lane + 96] = __float2bfloat16(o3 - __bfloat162float(h3));
}

__global__ __launch_bounds__(256) void k_post(bf16* __restrict__ kh, bf16* __restrict__ kl) {
    int wid  = blockIdx.x * 8 + (threadIdx.x >> 5);
    int lane = threadIdx.x & 31;
    int s = (wid >> 2) & (Ss - 1);
    const float* base = g_k + (size_t)wid * 128;
    float e0 = base[lane], e1 = base[lane + 32], e2 = base[lane + 64], e3 = base[lane + 96];
    float ssum = e0 * e0 + e1 * e1 + e2 * e2 + e3 * e3;
#pragma unroll
    for (int o = 16; o > 0; o >>= 1) ssum += __shfl_xor_sync(0xffffffffu, ssum, o);
    float r = rsqrtf(ssum * (1.0f / 128.0f) + 1e-6f);
    float c0 = g_cos[s * 64 + lane],      sn0 = g_sin[s * 64 + lane];
    float c1 = g_cos[s * 64 + lane + 32], sn1 = g_sin[s * 64 + lane + 32];
    float o0 = ( e0 * c0  + e2 * sn0) * r;
    float o1 = ( e1 * c1  + e3 * sn1) * r;
    float o2 = (-e0 * sn0 + e2 * c0 ) * r;
    float o3 = (-e1 * sn1 + e3 * c1 ) * r;
    size_t off = (size_t)wid * 128;
    bf16 h0 = __float2bfloat16(o0); kh[off + lane]      = h0; kl[off + lane]      = __float2bfloat16(o0 - __bfloat162float(h0));
    bf16 h1 = __float2bfloat16(o1); kh[off + lane + 32] = h1; kl[off + lane + 32] = __float2bfloat16(o1 - __bfloat162float(h1));
    bf16 h2 = __float2bfloat16(o2); kh[off + lane + 64] = h2; kl[off + lane + 64] = __float2bfloat16(o2 - __bfloat162float(h2));
    bf16 h3 = __float2bfloat16(o3); kh[off + lane + 96] = h3; kl[off + lane + 96] = __float2bfloat16(o3 - __bfloat162float(h3));
}

// ---------------- HMMA flash attention (split-bf16, R8-proven, BM=64) -------
#define FST 136
#define FQE (64 * FST)
#define FL2_SMEM ((2 * FQE + 8 * FQE) * 2)   // 174080 bytes

__device__ __forceinline__ void fl_load_kv(uint32_t sbase, int tid, int b, int kvh, int k0,
    const bf16* __restrict__ Kh, const bf16* __restrict__ Kl,
    const bf16* __restrict__ Vh, const bf16* __restrict__ Vl) {
#pragma unroll
    for (int it = 0; it < 8; it++) {
        int c = tid + it * 128;
        int r = c >> 4, o16 = c & 15;
        uint32_t d = sbase + (uint32_t)r * (FST * 2) + o16 * 16;
        size_t g = ((size_t)((b * Ss + k0 + r) * KVHh + kvh)) * HDd + o16 * 8;
        CP_ASYNC16(d,               Kh + g);
        CP_ASYNC16(d + 2 * FQE,     Kl + g);
        CP_ASYNC16(d + 4 * FQE,     Vh + g);
        CP_ASYNC16(d + 6 * FQE,     Vl + g);
    }
}

__global__ __launch_bounds__(128) void flash2(
    const bf16* __restrict__ Qh, const bf16* __restrict__ Ql,
    const bf16* __restrict__ Kh, const bf16* __restrict__ Kl,
    const bf16* __restrict__ Vh, const bf16* __restrict__ Vl,
    bf16* __restrict__ Oh, bf16* __restrict__ Ol) {
    extern __shared__ bf16 smb[];
    bf16* sQh = smb;
    bf16* sQl = smb + FQE;
    const uint32_t sm32 = smem_u32(smb);
    const int tid = threadIdx.x, wid = tid >> 5, lane = tid & 31;
    const int lr = lane >> 2, lc = lane & 3;
    const int qt = (Ss / 64 - 1) - blockIdx.x;
    const int h = blockIdx.y, b = blockIdx.z, kvh = h >> 2;
    const int q0 = qt * 64;
    const int wrow = wid * 16;

#pragma unroll
    for (int it = 0; it < 8; it++) {
        int c = tid + it * 128;
        int r = c >> 4, o = (c & 15) * 8;
        size_t g = (size_t)(b * Ss + q0 + r) * Dd + h * HDd + o;
        *(uint4*)(sQh + r * FST + o) = *(const uint4*)(Qh + g);
        *(uint4*)(sQl + r * FST + o) = *(const uint4*)(Ql + g);
    }
    fl_load_kv(sm32 + 4 * FQE, tid, b, kvh, 0, Kh, Kl, Vh, Vl);
    CP_COMMIT();

    float m0 = -1e30f, m1 = -1e30f, l0 = 0.0f, l1 = 0.0f;
    float O[16][4];
#pragma unroll
    for (int i = 0; i < 16; i++) { O[i][0] = O[i][1] = O[i][2] = O[i][3] = 0.0f; }

    for (int kt = 0; kt <= qt; kt++) {
        const int stage = kt & 1;
        if (kt < qt) {
            fl_load_kv(sm32 + 4 * FQE + (stage ^ 1) * 8 * FQE, tid, b, kvh, (kt + 1) * 64,
                       Kh, Kl, Vh, Vl);
            CP_COMMIT();
            CP_WAIT1();
        } else {
            CP_WAIT0();
        }
        __syncthreads();

        const bf16* sKh = smb + 2 * FQE + stage * 4 * FQE;
        const bf16* sKl = sKh + FQE;
        const uint32_t vh32 = sm32 + (2 * FQE + stage * 4 * FQE + 2 * FQE) * 2;
        const uint32_t vl32 = vh32 + 2 * FQE;

        float S[8][4];
#pragma unroll
        for (int nt = 0; nt < 8; nt++) S[nt][0] = S[nt][1] = S[nt][2] = S[nt][3] = 0.0f;

#pragma unroll
        for (int kst = 0; kst < 8; kst++) {
            const int pp2 = kst * 16 + lc * 2;
            const int r0 = wrow + lr;
            uint32_t qa_h[4], qa_l[4];
            qa_h[0] = *(const uint32_t*)(sQh + r0 * FST + pp2);
            qa_h[1] = *(const uint32_t*)(sQh + (r0 + 8) * FST + pp2);
            qa_h[2] = *(const uint32_t*)(sQh + r0 * FST + pp2 + 8);
            qa_h[3] = *(const uint32_t*)(sQh + (r0 + 8) * FST + pp2 + 8);
            qa_l[0] = *(const uint32_t*)(sQl + r0 * FST + pp2);
            qa_l[1] = *(const uint32_t*)(sQl + (r0 + 8) * FST + pp2);
            qa_l[2] = *(const uint32_t*)(sQl + r0 * FST + pp2 + 8);
            qa_l[3] = *(const uint32_t*)(sQl + (r0 + 8) * FST + pp2 + 8);
#pragma unroll
            for (int nt = 0; nt < 8; nt++) {
                const int n0 = nt * 8 + lr;
                uint32_t kb[2], klb[2];
                kb[0]  = *(const uint32_t*)(sKh + n0 * FST + pp2);
                kb[1]  = *(const uint32_t*)(sKh + n0 * FST + pp2 + 8);
                klb[0] = *(const uint32_t*)(sKl + n0 * FST + pp2);
                klb[1] = *(const uint32_t*)(sKl + n0 * FST + pp2 + 8);
                mma16816(S[nt], qa_h, kb);
                mma16816(S[nt], qa_h, klb);
                mma16816(S[nt], qa_l, kb);
            }
        }

        if (kt == qt) {
            const int row0 = q0 + wrow + lr;
#pragma unroll
            for (int nt = 0; nt < 8; nt++) {
                const int col = kt * 64 + nt * 8 + lc * 2;
                if (col     > row0)     S[nt][0] = -1e30f;
                if (col + 1 > row0)     S[nt][1] = -1e30f;
                if (col     > row0 + 8) S[nt][2] = -1e30f;
                if (col + 1 > row0 + 8) S[nt][3] = -1e30f;
            }
        }

        float rm0 = -1e30f, rm1 = -1e30f;
#pragma unroll
        for (int nt = 0; nt < 8; nt++) {
            rm0 = fmaxf(rm0, fmaxf(S[nt][0], S[nt][1]));
            rm1 = fmaxf(rm1, fmaxf(S[nt][2], S[nt][3]));
        }
        rm0 = fmaxf(rm0, __shfl_xor_sync(0xffffffffu, rm0, 1));
        rm0 = fmaxf(rm0, __shfl_xor_sync(0xffffffffu, rm0, 2));
        rm1 = fmaxf(rm1, __shfl_xor_sync(0xffffffffu, rm1, 1));
        rm1 = fmaxf(rm1, __shfl_xor_sync(0xffffffffu, rm1, 2));
        float mn0 = fmaxf(m0, rm0), mn1 = fmaxf(m1, rm1);
        float a0 = __expf(m0 - mn0), a1 = __expf(m1 - mn1);
        float rs0 = 0.0f, rs1 = 0.0f;
#pragma unroll
        for (int nt = 0; nt < 8; nt++) {
            S[nt][0] = __expf(S[nt][0] - mn0);
            S[nt][1] = __expf(S[nt][1] - mn0);
            S[nt][2] = __expf(S[nt][2] - mn1);
            S[nt][3] = __expf(S[nt][3] - mn1);
            rs0 += S[nt][0] + S[nt][1];
            rs1 += S[nt][2] + S[nt][3];
        }
        rs0 += __shfl_xor_sync(0xffffffffu, rs0, 1);
        rs0 += __shfl_xor_sync(0xffffffffu, rs0, 2);
        rs1 += __shfl_xor_sync(0xffffffffu, rs1, 1);
        rs1 += __shfl_xor_sync(0xffffffffu, rs1, 2);
        l0 = l0 * a0 + rs0;
        l1 = l1 * a1 + rs1;
        m0 = mn0; m1 = mn1;
#pragma unroll
        for (int i = 0; i < 16; i++) {
            O[i][0] *= a0; O[i][1] *= a0; O[i][2] *= a1; O[i][3] *= a1;
        }

        uint32_t pa_h[4][4], pa_l[4][4];
#pragma unroll
        for (int ks = 0; ks < 4; ks++) {
            splitpk(S[2 * ks][0],     S[2 * ks][1],     pa_h[ks][0], pa_l[ks][0]);
            splitpk(S[2 * ks][2],     S[2 * ks][3],     pa_h[ks][1], pa_l[ks][1]);
            splitpk(S[2 * ks + 1][0], S[2 * ks + 1][1], pa_h[ks][2], pa_l[ks][2]);
            splitpk(S[2 * ks + 1][2], S[2 * ks + 1][3], pa_h[ks][3], pa_l[ks][3]);
        }

#pragma unroll
        for (int ks = 0; ks < 4; ks++) {
            const uint32_t va = ((uint32_t)(16 * ks + (lane & 15)) * FST) * 2 + (lane >> 4) * 16;
#pragma unroll
            for (int ntp = 0; ntp < 8; ntp++) {
                uint32_t vh4[4], vl4[4];
                LDSM4T(vh4, vh32 + va + ntp * 32);
                LDSM4T(vl4, vl32 + va + ntp * 32);
                uint32_t b0[2] = {vh4[0], vh4[1]}, b1[2] = {vh4[2], vh4[3]};
                uint32_t c0[2] = {vl4[0], vl4[1]}, c1[2] = {vl4[2], vl4[3]};
                mma16816(O[2 * ntp],     pa_h[ks], b0);
                mma16816(O[2 * ntp],     pa_l[ks], b0);
                mma16816(O[2 * ntp],     pa_h[ks], c0);
                mma16816(O[2 * ntp + 1], pa_h[ks], b1);
                mma16816(O[2 * ntp + 1], pa_l[ks], b1);
                mma16816(O[2 * ntp + 1], pa_h[ks], c1);
            }
        }
        __syncthreads();
    }

    float il0 = 1.0f / l0, il1 = 1.0f / l1;
    size_t r0 = (size_t)(b * Ss + q0 + wrow + lr) * Dd + h * HDd;
    size_t r1 = r0 + 8 * (size_t)Dd;
#pragma unroll
    for (int nt = 0; nt < 16; nt++) {
        int cc = nt * 8 + lc * 2;
        uint32_t h0, lo0, h1, lo1;
        splitpk(O[nt][0] * il0, O[nt][1] * il0, h0, lo0);
        splitpk(O[nt][2] * il1, O[nt][3] * il1, h1, lo1);
        *(uint32_t*)(Oh + r0 + cc) = h0; *(uint32_t*)(Ol + r0 + cc) = lo0;
        *(uint32_t*)(Oh + r1 + cc) = h1; *(uint32_t*)(Ol + r1 + cc) = lo1;
    }
}

// ---------------- launch ----------------------------------------------------
extern "C" void kernel_launch(void* const* d_in, const int* in_sizes, int n_in,
                              void* d_out, int out_size) {
    const float* x    = (const float*)d_in[0];
    const float* Wq   = (const float*)d_in[1];
    const float* Wk   = (const float*)d_in[2];
    const float* Wv   = (const float*)d_in[3];
    const float* Wp   = (const float*)d_in[4];
    const float* gain = (const float*)d_in[5];
    float* out = (float*)d_out;

    float *q, *k, *v;
    bf16 *xh, *xl, *wh, *wl, *kh, *kl, *vh, *vl;
    cudaGetSymbolAddress((void**)&q,  g_q);
    cudaGetSymbolAddress((void**)&k,  g_k);
    cudaGetSymbolAddress((void**)&v,  g_v);
    cudaGetSymbolAddress((void**)&xh, g_xh);
    cudaGetSymbolAddress((void**)&xl, g_xl);
    cudaGetSymbolAddress((void**)&wh, g_wh);
    cudaGetSymbolAddress((void**)&wl, g_wl);
    cudaGetSymbolAddress((void**)&kh, g_kh);
    cudaGetSymbolAddress((void**)&kl, g_kl);
    cudaGetSymbolAddress((void**)&vh, g_vh);
    cudaGetSymbolAddress((void**)&vl, g_vl);

    cudaFuncSetAttribute(gemm_bf16s, cudaFuncAttributeMaxDynamicSharedMemorySize, GEMM_SMEM);
    cudaFuncSetAttribute(flash2,     cudaFuncAttributeMaxDynamicSharedMemorySize, FL2_SMEM);

    const int M = Bb * Ss;                 // 4096
    const int n4x = M * Dd / 4;
    const int n4w = Dd * Dd / 4;
    const int n4k = KVHh * HDd * Dd / 4;
    const int n4v = Bb * Ss * KVHh * HDd / 4;

    rope_table_kernel<<<(Ss * 64 + 255) / 256, 256>>>();

    cvt_split<<<(n4x + 255) / 256, 256>>>(x, xh, xl, n4x);

    cvt_split<<<(n4w + 255) / 256, 256>>>(Wq, wh, wl, n4w);
    gemm_bf16s<<<dim3(Dd / 128, M / 128), 256, GEMM_SMEM>>>(xh, xl, wh, wl, q, M, Dd, Dd);

    cvt_split<<<(n4k + 255) / 256, 256>>>(Wk, wh, wl, n4k);
    gemm_bf16s<<<dim3((KVHh * HDd) / 128, M / 128), 256, GEMM_SMEM>>>(xh, xl, wh, wl, k, M, KVHh * HDd, Dd);

    cvt_split<<<(n4k + 255) / 256, 256>>>(Wv, wh, wl, n4k);
    gemm_bf16s<<<dim3((KVHh * HDd) / 128, M / 128), 256, GEMM_SMEM>>>(xh, xl, wh, wl, v, M, KVHh * HDd, Dd);

    q_post<<<(Bb * Ss * Hh) / 8, 256>>>(gain, xh, xl);
    k_post<<<(Bb * Ss * KVHh) / 8, 256>>>(kh, kl);
    cvt_split<<<(n4v + 255) / 256, 256>>>(v, vh, vl, n4v);

    flash2<<<dim3(Ss / 64, Hh, Bb), 128, FL2_SMEM>>>(xh, xl, kh, kl, vh, vl, xh, xl);

    cvt_split<<<(n4w + 255) / 256, 256>>>(Wp, wh, wl, n4w);
    gemm_bf16s<<<dim3(Dd / 128, M / 128), 256, GEMM_SMEM>>>(xh, xl, wh, wl, out, M, Dd, Dd);
}

// round 14
// speedup vs baseline: 1.0895x; 1.0895x over previous
#include <cuda_runtime.h>
#include <cuda_bf16.h>
#include <math.h>
#include <stdint.h>

#define Bb   2
#define Ss   2048
#define Dd   2048
#define Hh   16
#define KVHh 4
#define HDd  128
#define NQKV 3072      // 2048 q + 512 k + 512 v

typedef __nv_bfloat16 bf16;

// ---------------- scratch (static device globals; no allocs) ----------------
__device__ float g_qkv[Bb * Ss * NQKV];        // fused qkv proj output
__device__ float g_cos[Ss * 64];
__device__ float g_sin[Ss * 64];
// split-bf16 operands. xh/xl: x-split -> Q-split (post) -> attn-out-split (flash)
__device__ __align__(16) bf16 g_xh[Bb * Ss * Dd];
__device__ __align__(16) bf16 g_xl[Bb * Ss * Dd];
__device__ __align__(16) bf16 g_wh[NQKV * Dd];
__device__ __align__(16) bf16 g_wl[NQKV * Dd];
__device__ __align__(16) bf16 g_kh[Bb * Ss * KVHh * HDd];
__device__ __align__(16) bf16 g_kl[Bb * Ss * KVHh * HDd];
__device__ __align__(16) bf16 g_vh[Bb * Ss * KVHh * HDd];
__device__ __align__(16) bf16 g_vl[Bb * Ss * KVHh * HDd];

// ---------------- helpers ----------------------------------------------------
__device__ __forceinline__ uint32_t smem_u32(const void* p) {
    uint32_t a;
    asm("{ .reg .u64 t; cvta.to.shared.u64 t, %1; cvt.u32.u64 %0, t; }" : "=r"(a) : "l"(p));
    return a;
}
#define CP_ASYNC16(dst, src) \
    asm volatile("cp.async.cg.shared.global [%0], [%1], 16;" :: "r"(dst), "l"(src) : "memory")
#define CP_COMMIT()  asm volatile("cp.async.commit_group;" ::: "memory")
#define CP_WAIT1()   asm volatile("cp.async.wait_group 1;" ::: "memory")
#define CP_WAIT0()   asm volatile("cp.async.wait_group 0;" ::: "memory")

__device__ __forceinline__ void mma16816(float* d, const uint32_t* a, const uint32_t* b) {
    asm volatile("mma.sync.aligned.m16n8k16.row.col.f32.bf16.bf16.f32 "
        "{%0,%1,%2,%3}, {%4,%5,%6,%7}, {%8,%9}, {%0,%1,%2,%3};"
        : "+f"(d[0]), "+f"(d[1]), "+f"(d[2]), "+f"(d[3])
        : "r"(a[0]), "r"(a[1]), "r"(a[2]), "r"(a[3]), "r"(b[0]), "r"(b[1]));
}
#define LDSM4T(r, a) \
    asm volatile("ldmatrix.sync.aligned.m8n8.x4.trans.shared.b16 {%0,%1,%2,%3}, [%4];" \
        : "=r"((r)[0]), "=r"((r)[1]), "=r"((r)[2]), "=r"((r)[3]) : "r"(a))

// pack two fp32 into bf16x2 (hi) and their residuals into bf16x2 (lo)
__device__ __forceinline__ void splitpk(float x0, float x1, uint32_t& hi, uint32_t& lo) {
    bf16 h0 = __float2bfloat16(x0), h1 = __float2bfloat16(x1);
    __nv_bfloat162 th = __halves2bfloat162(h0, h1);
    hi = *(uint32_t*)&th;
    bf16 r0 = __float2bfloat16(x0 - __bfloat162float(h0));
    bf16 r1 = __float2bfloat16(x1 - __bfloat162float(h1));
    __nv_bfloat162 tl = __halves2bfloat162(r0, r1);
    lo = *(uint32_t*)&tl;
}

// ---------------- RoPE table ------------------------------------------------
__global__ void rope_table_kernel() {
    int i = blockIdx.x * blockDim.x + threadIdx.x;
    if (i >= Ss * 64) return;
    int s = i >> 6, j = i & 63;
    float e   = (float)(2 * j) / (float)HDd;
    float inv = 1.0f / powf(10000.0f, e);
    float ang = (float)s * inv;
    g_cos[i] = (float)cos((double)ang);
    g_sin[i] = (float)sin((double)ang);
}

// ---------------- fp32 -> bf16 hi/lo split ----------------------------------
__global__ __launch_bounds__(256) void cvt_split(const float* __restrict__ src,
                                                 bf16* __restrict__ hi,
                                                 bf16* __restrict__ lo, int n4) {
    int i = blockIdx.x * blockDim.x + threadIdx.x;
    if (i >= n4) return;
    float4 v = ((const float4*)src)[i];
    uint32_t h0, l0, h1, l1;
    splitpk(v.x, v.y, h0, l0);
    splitpk(v.z, v.w, h1, l1);
    ((uint32_t*)hi)[2 * i] = h0; ((uint32_t*)hi)[2 * i + 1] = h1;
    ((uint32_t*)lo)[2 * i] = l0; ((uint32_t*)lo)[2 * i + 1] = l1;
}

// ---------------- split-bf16 HMMA GEMM: C = A @ B^T -------------------------
// R8-proven: scalar LDS fragment loads, CP_WAIT1 pipeline, stride-40 rows.
// ONLY change vs R8: the 3 split-term MMAs issued as 3 passes over (mt,nt)
// so same-accumulator HMMAs are 16 apart instead of back-to-back.
#define LDA        40
#define ARRB       (128 * LDA * 2)          // 10240 B per operand array
#define STAGEB     (4 * ARRB)               // 40960 B per stage
#define GEMM_SMEM  (2 * STAGEB)             // 81920 B

__device__ __forceinline__ void gemm_load_chunk(
    uint32_t sm32, int buf, int tid, int c,
    const bf16* __restrict__ Ah, const bf16* __restrict__ Al,
    const bf16* __restrict__ Bh, const bf16* __restrict__ Bl,
    int bm, int bn, int K) {
    int row = tid >> 2;
    int t16 = tid & 3;
    uint32_t so = sm32 + buf * STAGEB + (uint32_t)row * 80 + (uint32_t)t16 * 16;
    size_t gA = (size_t)(bm + row) * K + (size_t)c * 32 + t16 * 8;
    size_t gB = (size_t)(bn + row) * K + (size_t)c * 32 + t16 * 8;
    size_t stp = (size_t)64 * K;
    CP_ASYNC16(so,                       Ah + gA);
    CP_ASYNC16(so + 64 * 80,             Ah + gA + stp);
    CP_ASYNC16(so + ARRB,                Al + gA);
    CP_ASYNC16(so + ARRB + 64 * 80,      Al + gA + stp);
    CP_ASYNC16(so + 2 * ARRB,            Bh + gB);
    CP_ASYNC16(so + 2 * ARRB + 64 * 80,  Bh + gB + stp);
    CP_ASYNC16(so + 3 * ARRB,            Bl + gB);
    CP_ASYNC16(so + 3 * ARRB + 64 * 80,  Bl + gB + stp);
}

__global__ __launch_bounds__(256) void gemm_bf16s(
    const bf16* __restrict__ Ah, const bf16* __restrict__ Al,
    const bf16* __restrict__ Bh, const bf16* __restrict__ Bl,
    float* __restrict__ C, int M, int N, int K) {
    extern __shared__ char sm[];
    const uint32_t sm32 = smem_u32(sm);
    const int tid  = threadIdx.x;
    const int wid  = tid >> 5, lane = tid & 31;
    const int lr   = lane >> 2, lc = lane & 3;
    const int wm   = wid & 1;
    const int wn   = wid >> 1;
    const int bm = blockIdx.y * 128, bn = blockIdx.x * 128;

    float acc[4][4][4];
#pragma unroll
    for (int i = 0; i < 4; i++)
#pragma unroll
        for (int j = 0; j < 4; j++)
#pragma unroll
            for (int r = 0; r < 4; r++) acc[i][j][r] = 0.0f;

    const int NC = K >> 5;
    gemm_load_chunk(sm32, 0, tid, 0, Ah, Al, Bh, Bl, bm, bn, K);
    CP_COMMIT();

    for (int c = 0; c < NC; c++) {
        const int buf = c & 1;
        if (c + 1 < NC) {
            gemm_load_chunk(sm32, buf ^ 1, tid, c + 1, Ah, Al, Bh, Bl, bm, bn, K);
            CP_COMMIT();
            CP_WAIT1();
        } else {
            CP_WAIT0();
        }
        __syncthreads();

        const bf16* sA  = (const bf16*)(sm + buf * STAGEB);
        const bf16* sAl = sA + 128 * LDA;
        const bf16* sB  = sA + 2 * 128 * LDA;
        const bf16* sBl = sA + 3 * 128 * LDA;
#pragma unroll
        for (int kst = 0; kst < 2; kst++) {
            const int pp = kst * 8 + lc;
            uint32_t ah[4][4], al[4][4], bh[4][2], bl[4][2];
#pragma unroll
            for (int mt = 0; mt < 4; mt++) {
                int r0 = wm * 64 + mt * 16 + lr;
                ah[mt][0] = *(const uint32_t*)(sA + r0 * LDA + pp * 2);
                ah[mt][1] = *(const uint32_t*)(sA + (r0 + 8) * LDA + pp * 2);
                ah[mt][2] = *(const uint32_t*)(sA + r0 * LDA + (pp + 4) * 2);
                ah[mt][3] = *(const uint32_t*)(sA + (r0 + 8) * LDA + (pp + 4) * 2);
                al[mt][0] = *(const uint32_t*)(sAl + r0 * LDA + pp * 2);
                al[mt][1] = *(const uint32_t*)(sAl + (r0 + 8) * LDA + pp * 2);
                al[mt][2] = *(const uint32_t*)(sAl + r0 * LDA + (pp + 4) * 2);
                al[mt][3] = *(const uint32_t*)(sAl + (r0 + 8) * LDA + (pp + 4) * 2);
            }
#pragma unroll
            for (int nt = 0; nt < 4; nt++) {
                int n0 = wn * 32 + nt * 8 + lr;
                bh[nt][0] = *(const uint32_t*)(sB + n0 * LDA + pp * 2);
                bh[nt][1] = *(const uint32_t*)(sB + n0 * LDA + (pp + 4) * 2);
                bl[nt][0] = *(const uint32_t*)(sBl + n0 * LDA + pp * 2);
                bl[nt][1] = *(const uint32_t*)(sBl + n0 * LDA + (pp + 4) * 2);
            }
            // pass 1: Ah*Bh
#pragma unroll
            for (int mt = 0; mt < 4; mt++)
#pragma unroll
                for (int nt = 0; nt < 4; nt++)
                    mma16816(acc[mt][nt], ah[mt], bh[nt]);
            // pass 2: Ah*Bl
#pragma unroll
            for (int mt = 0; mt < 4; mt++)
#pragma unroll
                for (int nt = 0; nt < 4; nt++)
                    mma16816(acc[mt][nt], ah[mt], bl[nt]);
            // pass 3: Al*Bh
#pragma unroll
            for (int mt = 0; mt < 4; mt++)
#pragma unroll
                for (int nt = 0; nt < 4; nt++)
                    mma16816(acc[mt][nt], al[mt], bh[nt]);
        }
        __syncthreads();
    }

#pragma unroll
    for (int mt = 0; mt < 4; mt++) {
        int m = bm + wm * 64 + mt * 16 + lr;
#pragma unroll
        for (int nt = 0; nt < 4; nt++) {
            int n = bn + wn * 32 + nt * 8 + lc * 2;
            *(float2*)(C + (size_t)m * N + n)       = make_float2(acc[mt][nt][0], acc[mt][nt][1]);
            *(float2*)(C + (size_t)(m + 8) * N + n) = make_float2(acc[mt][nt][2], acc[mt][nt][3]);
        }
    }
}

// ---------------- q/kv epilogues: RMSNorm + RoPE (+gain) -> bf16 hi/lo ------
__global__ __launch_bounds__(256) void q_post(const float* __restrict__ gain,
                                              bf16* __restrict__ qh, bf16* __restrict__ ql) {
    int wid  = blockIdx.x * 8 + (threadIdx.x >> 5);   // 0..B*S*H-1
    int lane = threadIdx.x & 31;
    int h = wid & (Hh - 1);
    int row = wid >> 4;
    int s = row & (Ss - 1);
    const float* base = g_qkv + (size_t)row * NQKV + h * HDd;
    float e0 = base[lane], e1 = base[lane + 32], e2 = base[lane + 64], e3 = base[lane + 96];
    float ssum = e0 * e0 + e1 * e1 + e2 * e2 + e3 * e3;
#pragma unroll
    for (int o = 16; o > 0; o >>= 1) ssum += __shfl_xor_sync(0xffffffffu, ssum, o);
    float r = rsqrtf(ssum * (1.0f / 128.0f) + 1e-6f);
    float g = gain[h] * r * 0.08838834764831845f;
    float c0 = g_cos[s * 64 + lane],      sn0 = g_sin[s * 64 + lane];
    float c1 = g_cos[s * 64 + lane + 32], sn1 = g_sin[s * 64 + lane + 32];
    float o0 = ( e0 * c0  + e2 * sn0) * g;
    float o1 = ( e1 * c1  + e3 * sn1) * g;
    float o2 = (-e0 * sn0 + e2 * c0 ) * g;
    float o3 = (-e1 * sn1 + e3 * c1 ) * g;
    size_t off = (size_t)wid * 128;
    bf16 h0 = __float2bfloat16(o0); qh[off + lane]      = h0; ql[off + lane]      = __float2bfloat16(o0 - __bfloat162float(h0));
    bf16 h1 = __float2bfloat16(o1); qh[off + lane + 32] = h1; ql[off + lane + 32] = __float2bfloat16(o1 - __bfloat162float(h1));
    bf16 h2 = __float2bfloat16(o2); qh[off + lane + 64] = h2; ql[off + lane + 64] = __float2bfloat16(o2 - __bfloat162float(h2));
    bf16 h3 = __float2bfloat16(o3); qh[off + lane + 96] = h3; ql[off + lane + 96] = __float2bfloat16(o3 - __bfloat162float(h3));
}

__global__ __launch_bounds__(256) void kv_post(bf16* __restrict__ kh, bf16* __restrict__ kl,
                                               bf16* __restrict__ vh, bf16* __restrict__ vl) {
    int wid  = blockIdx.x * 8 + (threadIdx.x >> 5);   // 0..B*S*KVH-1
    int lane = threadIdx.x & 31;
    int kvh = wid & 3;
    int row = wid >> 2;
    int s = row & (Ss - 1);
    const float* kb = g_qkv + (size_t)row * NQKV + 2048 + kvh * HDd;
    const float* vb = kb + 512;
    float e0 = kb[lane], e1 = kb[lane + 32], e2 = kb[lane + 64], e3 = kb[lane + 96];
    float ssum = e0 * e0 + e1 * e1 + e2 * e2 + e3 * e3;
#pragma unroll
    for (int o = 16; o > 0; o >>= 1) ssum += __shfl_xor_sync(0xffffffffu, ssum, o);
    float r = rsqrtf(ssum * (1.0f / 128.0f) + 1e-6f);
    float c0 = g_cos[s * 64 + lane],      sn0 = g_sin[s * 64 + lane];
    float c1 = g_cos[s * 64 + lane + 32], sn1 = g_sin[s * 64 + lane + 32];
    float o0 = ( e0 * c0  + e2 * sn0) * r;
    float o1 = ( e1 * c1  + e3 * sn1) * r;
    float o2 = (-e0 * sn0 + e2 * c0 ) * r;
    float o3 = (-e1 * sn1 + e3 * c1 ) * r;
    size_t off = (size_t)wid * 128;
    bf16 h0 = __float2bfloat16(o0); kh[off + lane]      = h0; kl[off + lane]      = __float2bfloat16(o0 - __bfloat162float(h0));
    bf16 h1 = __float2bfloat16(o1); kh[off + lane + 32] = h1; kl[off + lane + 32] = __float2bfloat16(o1 - __bfloat162float(h1));
    bf16 h2 = __float2bfloat16(o2); kh[off + lane + 64] = h2; kl[off + lane + 64] = __float2bfloat16(o2 - __bfloat162float(h2));
    bf16 h3 = __float2bfloat16(o3); kh[off + lane + 96] = h3; kl[off + lane + 96] = __float2bfloat16(o3 - __bfloat162float(h3));
#pragma unroll
    for (int j = 0; j < 4; j++) {
        float f = vb[lane + 32 * j];
        bf16 fh = __float2bfloat16(f);
        vh[off + lane + 32 * j] = fh;
        vl[off + lane + 32 * j] = __float2bfloat16(f - __bfloat162float(fh));
    }
}

// ---------------- HMMA flash attention (split-bf16, R8-proven, BM=64) -------
#define FST 136
#define FQE (64 * FST)
#define FL2_SMEM ((2 * FQE + 8 * FQE) * 2)   // 174080 bytes

__device__ __forceinline__ void fl_load_kv(uint32_t sbase, int tid, int b, int kvh, int k0,
    const bf16* __restrict__ Kh, const bf16* __restrict__ Kl,
    const bf16* __restrict__ Vh, const bf16* __restrict__ Vl) {
#pragma unroll
    for (int it = 0; it < 8; it++) {
        int c = tid + it * 128;
        int r = c >> 4, o16 = c & 15;
        uint32_t d = sbase + (uint32_t)r * (FST * 2) + o16 * 16;
        size_t g = ((size_t)((b * Ss + k0 + r) * KVHh + kvh)) * HDd + o16 * 8;
        CP_ASYNC16(d,               Kh + g);
        CP_ASYNC16(d + 2 * FQE,     Kl + g);
        CP_ASYNC16(d + 4 * FQE,     Vh + g);
        CP_ASYNC16(d + 6 * FQE,     Vl + g);
    }
}

__global__ __launch_bounds__(128) void flash2(
    const bf16* __restrict__ Qh, const bf16* __restrict__ Ql,
    const bf16* __restrict__ Kh, const bf16* __restrict__ Kl,
    const bf16* __restrict__ Vh, const bf16* __restrict__ Vl,
    bf16* __restrict__ Oh, bf16* __restrict__ Ol) {
    extern __shared__ bf16 smb[];
    bf16* sQh = smb;
    bf16* sQl = smb + FQE;
    const uint32_t sm32 = smem_u32(smb);
    const int tid = threadIdx.x, wid = tid >> 5, lane = tid & 31;
    const int lr = lane >> 2, lc = lane & 3;
    const int qt = (Ss / 64 - 1) - blockIdx.x;
    const int h = blockIdx.y, b = blockIdx.z, kvh = h >> 2;
    const int q0 = qt * 64;
    const int wrow = wid * 16;

#pragma unroll
    for (int it = 0; it < 8; it++) {
        int c = tid + it * 128;
        int r = c >> 4, o = (c & 15) * 8;
        size_t g = (size_t)(b * Ss + q0 + r) * Dd + h * HDd + o;
        *(uint4*)(sQh + r * FST + o) = *(const uint4*)(Qh + g);
        *(uint4*)(sQl + r * FST + o) = *(const uint4*)(Ql + g);
    }
    fl_load_kv(sm32 + 4 * FQE, tid, b, kvh, 0, Kh, Kl, Vh, Vl);
    CP_COMMIT();

    float m0 = -1e30f, m1 = -1e30f, l0 = 0.0f, l1 = 0.0f;
    float O[16][4];
#pragma unroll
    for (int i = 0; i < 16; i++) { O[i][0] = O[i][1] = O[i][2] = O[i][3] = 0.0f; }

    for (int kt = 0; kt <= qt; kt++) {
        const int stage = kt & 1;
        if (kt < qt) {
            fl_load_kv(sm32 + 4 * FQE + (stage ^ 1) * 8 * FQE, tid, b, kvh, (kt + 1) * 64,
                       Kh, Kl, Vh, Vl);
            CP_COMMIT();
            CP_WAIT1();
        } else {
            CP_WAIT0();
        }
        __syncthreads();

        const bf16* sKh = smb + 2 * FQE + stage * 4 * FQE;
        const bf16* sKl = sKh + FQE;
        const uint32_t vh32 = sm32 + (2 * FQE + stage * 4 * FQE + 2 * FQE) * 2;
        const uint32_t vl32 = vh32 + 2 * FQE;

        float S[8][4];
#pragma unroll
        for (int nt = 0; nt < 8; nt++) S[nt][0] = S[nt][1] = S[nt][2] = S[nt][3] = 0.0f;

#pragma unroll
        for (int kst = 0; kst < 8; kst++) {
            const int pp2 = kst * 16 + lc * 2;
            const int r0 = wrow + lr;
            uint32_t qa_h[4], qa_l[4];
            qa_h[0] = *(const uint32_t*)(sQh + r0 * FST + pp2);
            qa_h[1] = *(const uint32_t*)(sQh + (r0 + 8) * FST + pp2);
            qa_h[2] = *(const uint32_t*)(sQh + r0 * FST + pp2 + 8);
            qa_h[3] = *(const uint32_t*)(sQh + (r0 + 8) * FST + pp2 + 8);
            qa_l[0] = *(const uint32_t*)(sQl + r0 * FST + pp2);
            qa_l[1] = *(const uint32_t*)(sQl + (r0 + 8) * FST + pp2);
            qa_l[2] = *(const uint32_t*)(sQl + r0 * FST + pp2 + 8);
            qa_l[3] = *(const uint32_t*)(sQl + (r0 + 8) * FST + pp2 + 8);
#pragma unroll
            for (int nt = 0; nt < 8; nt++) {
                const int n0 = nt * 8 + lr;
                uint32_t kb[2], klb[2];
                kb[0]  = *(const uint32_t*)(sKh + n0 * FST + pp2);
                kb[1]  = *(const uint32_t*)(sKh + n0 * FST + pp2 + 8);
                klb[0] = *(const uint32_t*)(sKl + n0 * FST + pp2);
                klb[1] = *(const uint32_t*)(sKl + n0 * FST + pp2 + 8);
                mma16816(S[nt], qa_h, kb);
                mma16816(S[nt], qa_h, klb);
                mma16816(S[nt], qa_l, kb);
            }
        }

        if (kt == qt) {
            const int row0 = q0 + wrow + lr;
#pragma unroll
            for (int nt = 0; nt < 8; nt++) {
                const int col = kt * 64 + nt * 8 + lc * 2;
                if (col     > row0)     S[nt][0] = -1e30f;
                if (col + 1 > row0)     S[nt][1] = -1e30f;
                if (col     > row0 + 8) S[nt][2] = -1e30f;
                if (col + 1 > row0 + 8) S[nt][3] = -1e30f;
            }
        }

        float rm0 = -1e30f, rm1 = -1e30f;
#pragma unroll
        for (int nt = 0; nt < 8; nt++) {
            rm0 = fmaxf(rm0, fmaxf(S[nt][0], S[nt][1]));
            rm1 = fmaxf(rm1, fmaxf(S[nt][2], S[nt][3]));
        }
        rm0 = fmaxf(rm0, __shfl_xor_sync(0xffffffffu, rm0, 1));
        rm0 = fmaxf(rm0, __shfl_xor_sync(0xffffffffu, rm0, 2));
        rm1 = fmaxf(rm1, __shfl_xor_sync(0xffffffffu, rm1, 1));
        rm1 = fmaxf(rm1, __shfl_xor_sync(0xffffffffu, rm1, 2));
        float mn0 = fmaxf(m0, rm0), mn1 = fmaxf(m1, rm1);
        float a0 = __expf(m0 - mn0), a1 = __expf(m1 - mn1);
        float rs0 = 0.0f, rs1 = 0.0f;
#pragma unroll
        for (int nt = 0; nt < 8; nt++) {
            S[nt][0] = __expf(S[nt][0] - mn0);
            S[nt][1] = __expf(S[nt][1] - mn0);
            S[nt][2] = __expf(S[nt][2] - mn1);
            S[nt][3] = __expf(S[nt][3] - mn1);
            rs0 += S[nt][0] + S[nt][1];
            rs1 += S[nt][2] + S[nt][3];
        }
        rs0 += __shfl_xor_sync(0xffffffffu, rs0, 1);
        rs0 += __shfl_xor_sync(0xffffffffu, rs0, 2);
        rs1 += __shfl_xor_sync(0xffffffffu, rs1, 1);
        rs1 += __shfl_xor_sync(0xffffffffu, rs1, 2);
        l0 = l0 * a0 + rs0;
        l1 = l1 * a1 + rs1;
        m0 = mn0; m1 = mn1;
#pragma unroll
        for (int i = 0; i < 16; i++) {
            O[i][0] *= a0; O[i][1] *= a0; O[i][2] *= a1; O[i][3] *= a1;
        }

        uint32_t pa_h[4][4], pa_l[4][4];
#pragma unroll
        for (int ks = 0; ks < 4; ks++) {
            splitpk(S[2 * ks][0],     S[2 * ks][1],     pa_h[ks][0], pa_l[ks][0]);
            splitpk(S[2 * ks][2],     S[2 * ks][3],     pa_h[ks][1], pa_l[ks][1]);
            splitpk(S[2 * ks + 1][0], S[2 * ks + 1][1], pa_h[ks][2], pa_l[ks][2]);
            splitpk(S[2 * ks + 1][2], S[2 * ks + 1][3], pa_h[ks][3], pa_l[ks][3]);
        }

#pragma unroll
        for (int ks = 0; ks < 4; ks++) {
            const uint32_t va = ((uint32_t)(16 * ks + (lane & 15)) * FST) * 2 + (lane >> 4) * 16;
#pragma unroll
            for (int ntp = 0; ntp < 8; ntp++) {
                uint32_t vh4[4], vl4[4];
                LDSM4T(vh4, vh32 + va + ntp * 32);
                LDSM4T(vl4, vl32 + va + ntp * 32);
                uint32_t b0[2] = {vh4[0], vh4[1]}, b1[2] = {vh4[2], vh4[3]};
                uint32_t c0[2] = {vl4[0], vl4[1]}, c1[2] = {vl4[2], vl4[3]};
                mma16816(O[2 * ntp],     pa_h[ks], b0);
                mma16816(O[2 * ntp],     pa_l[ks], b0);
                mma16816(O[2 * ntp],     pa_h[ks], c0);
                mma16816(O[2 * ntp + 1], pa_h[ks], b1);
                mma16816(O[2 * ntp + 1], pa_l[ks], b1);
                mma16816(O[2 * ntp + 1], pa_h[ks], c1);
            }
        }
        __syncthreads();
    }

    float il0 = 1.0f / l0, il1 = 1.0f / l1;
    size_t r0 = (size_t)(b * Ss + q0 + wrow + lr) * Dd + h * HDd;
    size_t r1 = r0 + 8 * (size_t)Dd;
#pragma unroll
    for (int nt = 0; nt < 16; nt++) {
        int cc = nt * 8 + lc * 2;
        uint32_t h0, lo0, h1, lo1;
        splitpk(O[nt][0] * il0, O[nt][1] * il0, h0, lo0);
        splitpk(O[nt][2] * il1, O[nt][3] * il1, h1, lo1);
        *(uint32_t*)(Oh + r0 + cc) = h0; *(uint32_t*)(Ol + r0 + cc) = lo0;
        *(uint32_t*)(Oh + r1 + cc) = h1; *(uint32_t*)(Ol + r1 + cc) = lo1;
    }
}

// ---------------- launch ----------------------------------------------------
extern "C" void kernel_launch(void* const* d_in, const int* in_sizes, int n_in,
                              void* d_out, int out_size) {
    const float* x    = (const float*)d_in[0];
    const float* Wq   = (const float*)d_in[1];
    const float* Wk   = (const float*)d_in[2];
    const float* Wv   = (const float*)d_in[3];
    const float* Wp   = (const float*)d_in[4];
    const float* gain = (const float*)d_in[5];
    float* out = (float*)d_out;

    float* qkv;
    bf16 *xh, *xl, *wh, *wl, *kh, *kl, *vh, *vl;
    cudaGetSymbolAddress((void**)&qkv, g_qkv);
    cudaGetSymbolAddress((void**)&xh, g_xh);
    cudaGetSymbolAddress((void**)&xl, g_xl);
    cudaGetSymbolAddress((void**)&wh, g_wh);
    cudaGetSymbolAddress((void**)&wl, g_wl);
    cudaGetSymbolAddress((void**)&kh, g_kh);
    cudaGetSymbolAddress((void**)&kl, g_kl);
    cudaGetSymbolAddress((void**)&vh, g_vh);
    cudaGetSymbolAddress((void**)&vl, g_vl);

    cudaFuncSetAttribute(gemm_bf16s, cudaFuncAttributeMaxDynamicSharedMemorySize, GEMM_SMEM);
    cudaFuncSetAttribute(flash2,     cudaFuncAttributeMaxDynamicSharedMemorySize, FL2_SMEM);

    const int M = Bb * Ss;                 // 4096
    const int n4x = M * Dd / 4;
    const int n4w = Dd * Dd / 4;
    const int n4k = 512 * Dd / 4;

    rope_table_kernel<<<(Ss * 64 + 255) / 256, 256>>>();

    cvt_split<<<(n4x + 255) / 256, 256>>>(x, xh, xl, n4x);

    // fused weight: rows 0-2047 Wq, 2048-2559 Wk, 2560-3071 Wv
    cvt_split<<<(n4w + 255) / 256, 256>>>(Wq, wh, wl, n4w);
    cvt_split<<<(n4k + 255) / 256, 256>>>(Wk, wh + (size_t)2048 * Dd, wl + (size_t)2048 * Dd, n4k);
    cvt_split<<<(n4k + 255) / 256, 256>>>(Wv, wh + (size_t)2560 * Dd, wl + (size_t)2560 * Dd, n4k);

    gemm_bf16s<<<dim3(NQKV / 128, M / 128), 256, GEMM_SMEM>>>(xh, xl, wh, wl, qkv, M, NQKV, Dd);

    q_post<<<(Bb * Ss * Hh) / 8, 256>>>(gain, xh, xl);
    kv_post<<<(Bb * Ss * KVHh) / 8, 256>>>(kh, kl, vh, vl);

    flash2<<<dim3(Ss / 64, Hh, Bb), 128, FL2_SMEM>>>(xh, xl, kh, kl, vh, vl, xh, xl);

    cvt_split<<<(n4w + 255) / 256, 256>>>(Wp, wh, wl, n4w);
    gemm_bf16s<<<dim3(Dd / 128, M / 128), 256, GEMM_SMEM>>>(xh, xl, wh, wl, out, M, Dd, Dd);
}

// round 15
// speedup vs baseline: 1.3282x; 1.2191x over previous
#include <cuda_runtime.h>
#include <cuda_bf16.h>
#include <cuda_fp16.h>
#include <math.h>
#include <stdint.h>

#define Bb   2
#define Ss   2048
#define Dd   2048
#define Hh   16
#define KVHh 4
#define HDd  128
#define NQKV 3072      // col layout in g_qkv: 0-2047 q, 2048-2559 k, 2560-3071 v
#define NQK  2560

typedef __nv_bfloat16 bf16;

// ---------------- scratch (static device globals; no allocs) ----------------
__device__ float g_qkv[Bb * Ss * NQKV];
__device__ float g_cos[Ss * 64];
__device__ float g_sin[Ss * 64];
// bf16 split operands (precise path)
__device__ __align__(16) bf16 g_xh[Bb * Ss * Dd];
__device__ __align__(16) bf16 g_xl[Bb * Ss * Dd];
__device__ __align__(16) bf16 g_wh[NQK * Dd];
__device__ __align__(16) bf16 g_wl[NQK * Dd];
__device__ __align__(16) bf16 g_kh[Bb * Ss * KVHh * HDd];
__device__ __align__(16) bf16 g_kl[Bb * Ss * KVHh * HDd];
__device__ __align__(16) bf16 g_vh[Bb * Ss * KVHh * HDd];
__device__ __align__(16) bf16 g_vl[Bb * Ss * KVHh * HDd];
// fp16 operands (linear path): xf = x-fp16, later overwritten by attn-out-fp16
__device__ __align__(16) __half g_xf[Bb * Ss * Dd];
__device__ __align__(16) __half g_wf[Dd * Dd];

// ---------------- helpers ----------------------------------------------------
__device__ __forceinline__ uint32_t smem_u32(const void* p) {
    uint32_t a;
    asm("{ .reg .u64 t; cvta.to.shared.u64 t, %1; cvt.u32.u64 %0, t; }" : "=r"(a) : "l"(p));
    return a;
}
#define CP_ASYNC16(dst, src) \
    asm volatile("cp.async.cg.shared.global [%0], [%1], 16;" :: "r"(dst), "l"(src) : "memory")
#define CP_COMMIT()  asm volatile("cp.async.commit_group;" ::: "memory")
#define CP_WAIT1()   asm volatile("cp.async.wait_group 1;" ::: "memory")
#define CP_WAIT0()   asm volatile("cp.async.wait_group 0;" ::: "memory")

__device__ __forceinline__ void mma16816(float* d, const uint32_t* a, const uint32_t* b) {
    asm volatile("mma.sync.aligned.m16n8k16.row.col.f32.bf16.bf16.f32 "
        "{%0,%1,%2,%3}, {%4,%5,%6,%7}, {%8,%9}, {%0,%1,%2,%3};"
        : "+f"(d[0]), "+f"(d[1]), "+f"(d[2]), "+f"(d[3])
        : "r"(a[0]), "r"(a[1]), "r"(a[2]), "r"(a[3]), "r"(b[0]), "r"(b[1]));
}
__device__ __forceinline__ void mma16816h(float* d, const uint32_t* a, const uint32_t* b) {
    asm volatile("mma.sync.aligned.m16n8k16.row.col.f32.f16.f16.f32 "
        "{%0,%1,%2,%3}, {%4,%5,%6,%7}, {%8,%9}, {%0,%1,%2,%3};"
        : "+f"(d[0]), "+f"(d[1]), "+f"(d[2]), "+f"(d[3])
        : "r"(a[0]), "r"(a[1]), "r"(a[2]), "r"(a[3]), "r"(b[0]), "r"(b[1]));
}
#define LDSM4T(r, a) \
    asm volatile("ldmatrix.sync.aligned.m8n8.x4.trans.shared.b16 {%0,%1,%2,%3}, [%4];" \
        : "=r"((r)[0]), "=r"((r)[1]), "=r"((r)[2]), "=r"((r)[3]) : "r"(a))

// pack two fp32 into bf16x2 (hi) and their residuals into bf16x2 (lo)
__device__ __forceinline__ void splitpk(float x0, float x1, uint32_t& hi, uint32_t& lo) {
    bf16 h0 = __float2bfloat16(x0), h1 = __float2bfloat16(x1);
    __nv_bfloat162 th = __halves2bfloat162(h0, h1);
    hi = *(uint32_t*)&th;
    bf16 r0 = __float2bfloat16(x0 - __bfloat162float(h0));
    bf16 r1 = __float2bfloat16(x1 - __bfloat162float(h1));
    __nv_bfloat162 tl = __halves2bfloat162(r0, r1);
    lo = *(uint32_t*)&tl;
}

// ---------------- RoPE table ------------------------------------------------
__global__ void rope_table_kernel() {
    int i = blockIdx.x * blockDim.x + threadIdx.x;
    if (i >= Ss * 64) return;
    int s = i >> 6, j = i & 63;
    float e   = (float)(2 * j) / (float)HDd;
    float inv = 1.0f / powf(10000.0f, e);
    float ang = (float)s * inv;
    g_cos[i] = (float)cos((double)ang);
    g_sin[i] = (float)sin((double)ang);
}

// ---------------- fp32 -> bf16 hi/lo split ----------------------------------
__global__ __launch_bounds__(256) void cvt_split(const float* __restrict__ src,
                                                 bf16* __restrict__ hi,
                                                 bf16* __restrict__ lo, int n4) {
    int i = blockIdx.x * blockDim.x + threadIdx.x;
    if (i >= n4) return;
    float4 v = ((const float4*)src)[i];
    uint32_t h0, l0, h1, l1;
    splitpk(v.x, v.y, h0, l0);
    splitpk(v.z, v.w, h1, l1);
    ((uint32_t*)hi)[2 * i] = h0; ((uint32_t*)hi)[2 * i + 1] = h1;
    ((uint32_t*)lo)[2 * i] = l0; ((uint32_t*)lo)[2 * i + 1] = l1;
}

// ---------------- fp32 -> fp16 ----------------------------------------------
__global__ __launch_bounds__(256) void cvt_half(const float* __restrict__ src,
                                                __half* __restrict__ dst, int n4) {
    int i = blockIdx.x * blockDim.x + threadIdx.x;
    if (i >= n4) return;
    float4 v = ((const float4*)src)[i];
    ((__half2*)dst)[2 * i]     = __floats2half2_rn(v.x, v.y);
    ((__half2*)dst)[2 * i + 1] = __floats2half2_rn(v.z, v.w);
}

// ---------------- split-bf16 HMMA GEMM (R14-proven) -------------------------
#define LDA        40
#define ARRB       (128 * LDA * 2)
#define STAGEB     (4 * ARRB)
#define GEMM_SMEM  (2 * STAGEB)

__device__ __forceinline__ void gemm_load_chunk(
    uint32_t sm32, int buf, int tid, int c,
    const bf16* __restrict__ Ah, const bf16* __restrict__ Al,
    const bf16* __restrict__ Bh, const bf16* __restrict__ Bl,
    int bm, int bn, int K) {
    int row = tid >> 2;
    int t16 = tid & 3;
    uint32_t so = sm32 + buf * STAGEB + (uint32_t)row * 80 + (uint32_t)t16 * 16;
    size_t gA = (size_t)(bm + row) * K + (size_t)c * 32 + t16 * 8;
    size_t gB = (size_t)(bn + row) * K + (size_t)c * 32 + t16 * 8;
    size_t stp = (size_t)64 * K;
    CP_ASYNC16(so,                       Ah + gA);
    CP_ASYNC16(so + 64 * 80,             Ah + gA + stp);
    CP_ASYNC16(so + ARRB,                Al + gA);
    CP_ASYNC16(so + ARRB + 64 * 80,      Al + gA + stp);
    CP_ASYNC16(so + 2 * ARRB,            Bh + gB);
    CP_ASYNC16(so + 2 * ARRB + 64 * 80,  Bh + gB + stp);
    CP_ASYNC16(so + 3 * ARRB,            Bl + gB);
    CP_ASYNC16(so + 3 * ARRB + 64 * 80,  Bl + gB + stp);
}

__global__ __launch_bounds__(256) void gemm_bf16s(
    const bf16* __restrict__ Ah, const bf16* __restrict__ Al,
    const bf16* __restrict__ Bh, const bf16* __restrict__ Bl,
    float* __restrict__ C, int M, int N, int K, int ldc) {
    extern __shared__ char sm[];
    const uint32_t sm32 = smem_u32(sm);
    const int tid  = threadIdx.x;
    const int wid  = tid >> 5, lane = tid & 31;
    const int lr   = lane >> 2, lc = lane & 3;
    const int wm   = wid & 1;
    const int wn   = wid >> 1;
    const int bm = blockIdx.y * 128, bn = blockIdx.x * 128;

    float acc[4][4][4];
#pragma unroll
    for (int i = 0; i < 4; i++)
#pragma unroll
        for (int j = 0; j < 4; j++)
#pragma unroll
            for (int r = 0; r < 4; r++) acc[i][j][r] = 0.0f;

    const int NC = K >> 5;
    gemm_load_chunk(sm32, 0, tid, 0, Ah, Al, Bh, Bl, bm, bn, K);
    CP_COMMIT();

    for (int c = 0; c < NC; c++) {
        const int buf = c & 1;
        if (c + 1 < NC) {
            gemm_load_chunk(sm32, buf ^ 1, tid, c + 1, Ah, Al, Bh, Bl, bm, bn, K);
            CP_COMMIT();
            CP_WAIT1();
        } else {
            CP_WAIT0();
        }
        __syncthreads();

        const bf16* sA  = (const bf16*)(sm + buf * STAGEB);
        const bf16* sAl = sA + 128 * LDA;
        const bf16* sB  = sA + 2 * 128 * LDA;
        const bf16* sBl = sA + 3 * 128 * LDA;
#pragma unroll
        for (int kst = 0; kst < 2; kst++) {
            const int pp = kst * 8 + lc;
            uint32_t ah[4][4], al[4][4], bh[4][2], bl[4][2];
#pragma unroll
            for (int mt = 0; mt < 4; mt++) {
                int r0 = wm * 64 + mt * 16 + lr;
                ah[mt][0] = *(const uint32_t*)(sA + r0 * LDA + pp * 2);
                ah[mt][1] = *(const uint32_t*)(sA + (r0 + 8) * LDA + pp * 2);
                ah[mt][2] = *(const uint32_t*)(sA + r0 * LDA + (pp + 4) * 2);
                ah[mt][3] = *(const uint32_t*)(sA + (r0 + 8) * LDA + (pp + 4) * 2);
                al[mt][0] = *(const uint32_t*)(sAl + r0 * LDA + pp * 2);
                al[mt][1] = *(const uint32_t*)(sAl + (r0 + 8) * LDA + pp * 2);
                al[mt][2] = *(const uint32_t*)(sAl + r0 * LDA + (pp + 4) * 2);
                al[mt][3] = *(const uint32_t*)(sAl + (r0 + 8) * LDA + (pp + 4) * 2);
            }
#pragma unroll
            for (int nt = 0; nt < 4; nt++) {
                int n0 = wn * 32 + nt * 8 + lr;
                bh[nt][0] = *(const uint32_t*)(sB + n0 * LDA + pp * 2);
                bh[nt][1] = *(const uint32_t*)(sB + n0 * LDA + (pp + 4) * 2);
                bl[nt][0] = *(const uint32_t*)(sBl + n0 * LDA + pp * 2);
                bl[nt][1] = *(const uint32_t*)(sBl + n0 * LDA + (pp + 4) * 2);
            }
#pragma unroll
            for (int mt = 0; mt < 4; mt++)
#pragma unroll
                for (int nt = 0; nt < 4; nt++)
                    mma16816(acc[mt][nt], ah[mt], bh[nt]);
#pragma unroll
            for (int mt = 0; mt < 4; mt++)
#pragma unroll
                for (int nt = 0; nt < 4; nt++)
                    mma16816(acc[mt][nt], ah[mt], bl[nt]);
#pragma unroll
            for (int mt = 0; mt < 4; mt++)
#pragma unroll
                for (int nt = 0; nt < 4; nt++)
                    mma16816(acc[mt][nt], al[mt], bh[nt]);
        }
        __syncthreads();
    }

#pragma unroll
    for (int mt = 0; mt < 4; mt++) {
        int m = bm + wm * 64 + mt * 16 + lr;
#pragma unroll
        for (int nt = 0; nt < 4; nt++) {
            int n = bn + wn * 32 + nt * 8 + lc * 2;
            *(float2*)(C + (size_t)m * ldc + n)       = make_float2(acc[mt][nt][0], acc[mt][nt][1]);
            *(float2*)(C + (size_t)(m + 8) * ldc + n) = make_float2(acc[mt][nt][2], acc[mt][nt][3]);
        }
    }
}

// ---------------- plain fp16 HMMA GEMM (1-term, linear paths) ----------------
#define ARRB2       (128 * LDA * 2)        // 10240 B per operand
#define STAGE2      (2 * ARRB2)            // 20480 B per stage
#define GEMM2_SMEM  (2 * STAGE2)           // 40960 B

__device__ __forceinline__ void gemm16_load(
    uint32_t sm32, int buf, int tid, int c,
    const __half* __restrict__ A, const __half* __restrict__ B,
    int bm, int bn, int K) {
    int row = tid >> 2;
    int t16 = tid & 3;
    uint32_t so = sm32 + buf * STAGE2 + (uint32_t)row * 80 + (uint32_t)t16 * 16;
    size_t gA = (size_t)(bm + row) * K + (size_t)c * 32 + t16 * 8;
    size_t gB = (size_t)(bn + row) * K + (size_t)c * 32 + t16 * 8;
    size_t stp = (size_t)64 * K;
    CP_ASYNC16(so,                   A + gA);
    CP_ASYNC16(so + 64 * 80,         A + gA + stp);
    CP_ASYNC16(so + ARRB2,           B + gB);
    CP_ASYNC16(so + ARRB2 + 64 * 80, B + gB + stp);
}

__global__ __launch_bounds__(256) void gemm_fp16s(
    const __half* __restrict__ A, const __half* __restrict__ B,
    float* __restrict__ C, int M, int N, int K, int ldc) {
    extern __shared__ char sm[];
    const uint32_t sm32 = smem_u32(sm);
    const int tid  = threadIdx.x;
    const int wid  = tid >> 5, lane = tid & 31;
    const int lr   = lane >> 2, lc = lane & 3;
    const int wm   = wid & 1;
    const int wn   = wid >> 1;
    const int bm = blockIdx.y * 128, bn = blockIdx.x * 128;

    float acc[4][4][4];
#pragma unroll
    for (int i = 0; i < 4; i++)
#pragma unroll
        for (int j = 0; j < 4; j++)
#pragma unroll
            for (int r = 0; r < 4; r++) acc[i][j][r] = 0.0f;

    const int NC = K >> 5;
    gemm16_load(sm32, 0, tid, 0, A, B, bm, bn, K);
    CP_COMMIT();

    for (int c = 0; c < NC; c++) {
        const int buf = c & 1;
        if (c + 1 < NC) {
            gemm16_load(sm32, buf ^ 1, tid, c + 1, A, B, bm, bn, K);
            CP_COMMIT();
            CP_WAIT1();
        } else {
            CP_WAIT0();
        }
        __syncthreads();

        const __half* sA = (const __half*)(sm + buf * STAGE2);
        const __half* sB = sA + 128 * LDA;
#pragma unroll
        for (int kst = 0; kst < 2; kst++) {
            const int pp = kst * 8 + lc;
            uint32_t ah[4][4], bh[4][2];
#pragma unroll
            for (int mt = 0; mt < 4; mt++) {
                int r0 = wm * 64 + mt * 16 + lr;
                ah[mt][0] = *(const uint32_t*)(sA + r0 * LDA + pp * 2);
                ah[mt][1] = *(const uint32_t*)(sA + (r0 + 8) * LDA + pp * 2);
                ah[mt][2] = *(const uint32_t*)(sA + r0 * LDA + (pp + 4) * 2);
                ah[mt][3] = *(const uint32_t*)(sA + (r0 + 8) * LDA + (pp + 4) * 2);
            }
#pragma unroll
            for (int nt = 0; nt < 4; nt++) {
                int n0 = wn * 32 + nt * 8 + lr;
                bh[nt][0] = *(const uint32_t*)(sB + n0 * LDA + pp * 2);
                bh[nt][1] = *(const uint32_t*)(sB + n0 * LDA + (pp + 4) * 2);
            }
#pragma unroll
            for (int mt = 0; mt < 4; mt++)
#pragma unroll
                for (int nt = 0; nt < 4; nt++)
                    mma16816h(acc[mt][nt], ah[mt], bh[nt]);
        }
        __syncthreads();
    }

#pragma unroll
    for (int mt = 0; mt < 4; mt++) {
        int m = bm + wm * 64 + mt * 16 + lr;
#pragma unroll
        for (int nt = 0; nt < 4; nt++) {
            int n = bn + wn * 32 + nt * 8 + lc * 2;
            *(float2*)(C + (size_t)m * ldc + n)       = make_float2(acc[mt][nt][0], acc[mt][nt][1]);
            *(float2*)(C + (size_t)(m + 8) * ldc + n) = make_float2(acc[mt][nt][2], acc[mt][nt][3]);
        }
    }
}

// ---------------- q/kv epilogues: RMSNorm + RoPE (+gain) -> bf16 hi/lo ------
__global__ __launch_bounds__(256) void q_post(const float* __restrict__ gain,
                                              bf16* __restrict__ qh, bf16* __restrict__ ql) {
    int wid  = blockIdx.x * 8 + (threadIdx.x >> 5);
    int lane = threadIdx.x & 31;
    int h = wid & (Hh - 1);
    int row = wid >> 4;
    int s = row & (Ss - 1);
    const float* base = g_qkv + (size_t)row * NQKV + h * HDd;
    float e0 = base[lane], e1 = base[lane + 32], e2 = base[lane + 64], e3 = base[lane + 96];
    float ssum = e0 * e0 + e1 * e1 + e2 * e2 + e3 * e3;
#pragma unroll
    for (int o = 16; o > 0; o >>= 1) ssum += __shfl_xor_sync(0xffffffffu, ssum, o);
    float r = rsqrtf(ssum * (1.0f / 128.0f) + 1e-6f);
    float g = gain[h] * r * 0.08838834764831845f;
    float c0 = g_cos[s * 64 + lane],      sn0 = g_sin[s * 64 + lane];
    float c1 = g_cos[s * 64 + lane + 32], sn1 = g_sin[s * 64 + lane + 32];
    float o0 = ( e0 * c0  + e2 * sn0) * g;
    float o1 = ( e1 * c1  + e3 * sn1) * g;
    float o2 = (-e0 * sn0 + e2 * c0 ) * g;
    float o3 = (-e1 * sn1 + e3 * c1 ) * g;
    size_t off = (size_t)wid * 128;
    bf16 h0 = __float2bfloat16(o0); qh[off + lane]      = h0; ql[off + lane]      = __float2bfloat16(o0 - __bfloat162float(h0));
    bf16 h1 = __float2bfloat16(o1); qh[off + lane + 32] = h1; ql[off + lane + 32] = __float2bfloat16(o1 - __bfloat162float(h1));
    bf16 h2 = __float2bfloat16(o2); qh[off + lane + 64] = h2; ql[off + lane + 64] = __float2bfloat16(o2 - __bfloat162float(h2));
    bf16 h3 = __float2bfloat16(o3); qh[off + lane + 96] = h3; ql[off + lane + 96] = __float2bfloat16(o3 - __bfloat162float(h3));
}

__global__ __launch_bounds__(256) void kv_post(bf16* __restrict__ kh, bf16* __restrict__ kl,
                                               bf16* __restrict__ vh, bf16* __restrict__ vl) {
    int wid  = blockIdx.x * 8 + (threadIdx.x >> 5);
    int lane = threadIdx.x & 31;
    int kvh = wid & 3;
    int row = wid >> 2;
    int s = row & (Ss - 1);
    const float* kb = g_qkv + (size_t)row * NQKV + 2048 + kvh * HDd;
    const float* vb = kb + 512;
    float e0 = kb[lane], e1 = kb[lane + 32], e2 = kb[lane + 64], e3 = kb[lane + 96];
    float ssum = e0 * e0 + e1 * e1 + e2 * e2 + e3 * e3;
#pragma unroll
    for (int o = 16; o > 0; o >>= 1) ssum += __shfl_xor_sync(0xffffffffu, ssum, o);
    float r = rsqrtf(ssum * (1.0f / 128.0f) + 1e-6f);
    float c0 = g_cos[s * 64 + lane],      sn0 = g_sin[s * 64 + lane];
    float c1 = g_cos[s * 64 + lane + 32], sn1 = g_sin[s * 64 + lane + 32];
    float o0 = ( e0 * c0  + e2 * sn0) * r;
    float o1 = ( e1 * c1  + e3 * sn1) * r;
    float o2 = (-e0 * sn0 + e2 * c0 ) * r;
    float o3 = (-e1 * sn1 + e3 * c1 ) * r;
    size_t off = (size_t)wid * 128;
    bf16 h0 = __float2bfloat16(o0); kh[off + lane]      = h0; kl[off + lane]      = __float2bfloat16(o0 - __bfloat162float(h0));
    bf16 h1 = __float2bfloat16(o1); kh[off + lane + 32] = h1; kl[off + lane + 32] = __float2bfloat16(o1 - __bfloat162float(h1));
    bf16 h2 = __float2bfloat16(o2); kh[off + lane + 64] = h2; kl[off + lane + 64] = __float2bfloat16(o2 - __bfloat162float(h2));
    bf16 h3 = __float2bfloat16(o3); kh[off + lane + 96] = h3; kl[off + lane + 96] = __float2bfloat16(o3 - __bfloat162float(h3));
#pragma unroll
    for (int j = 0; j < 4; j++) {
        float f = vb[lane + 32 * j];
        bf16 fh = __float2bfloat16(f);
        vh[off + lane + 32 * j] = fh;
        vl[off + lane + 32 * j] = __float2bfloat16(f - __bfloat162float(fh));
    }
}

// ---------------- HMMA flash attention (split-bf16, R8-proven, BM=64) -------
// Epilogue now writes fp16 (for the fp16 out-proj GEMM).
#define FST 136
#define FQE (64 * FST)
#define FL2_SMEM ((2 * FQE + 8 * FQE) * 2)   // 174080 bytes

__device__ __forceinline__ void fl_load_kv(uint32_t sbase, int tid, int b, int kvh, int k0,
    const bf16* __restrict__ Kh, const bf16* __restrict__ Kl,
    const bf16* __restrict__ Vh, const bf16* __restrict__ Vl) {
#pragma unroll
    for (int it = 0; it < 8; it++) {
        int c = tid + it * 128;
        int r = c >> 4, o16 = c & 15;
        uint32_t d = sbase + (uint32_t)r * (FST * 2) + o16 * 16;
        size_t g = ((size_t)((b * Ss + k0 + r) * KVHh + kvh)) * HDd + o16 * 8;
        CP_ASYNC16(d,               Kh + g);
        CP_ASYNC16(d + 2 * FQE,     Kl + g);
        CP_ASYNC16(d + 4 * FQE,     Vh + g);
        CP_ASYNC16(d + 6 * FQE,     Vl + g);
    }
}

__global__ __launch_bounds__(128) void flash2(
    const bf16* __restrict__ Qh, const bf16* __restrict__ Ql,
    const bf16* __restrict__ Kh, const bf16* __restrict__ Kl,
    const bf16* __restrict__ Vh, const bf16* __restrict__ Vl,
    __half* __restrict__ Of) {
    extern __shared__ bf16 smb[];
    bf16* sQh = smb;
    bf16* sQl = smb + FQE;
    const uint32_t sm32 = smem_u32(smb);
    const int tid = threadIdx.x, wid = tid >> 5, lane = tid & 31;
    const int lr = lane >> 2, lc = lane & 3;
    const int qt = (Ss / 64 - 1) - blockIdx.x;
    const int h = blockIdx.y, b = blockIdx.z, kvh = h >> 2;
    const int q0 = qt * 64;
    const int wrow = wid * 16;

#pragma unroll
    for (int it = 0; it < 8; it++) {
        int c = tid + it * 128;
        int r = c >> 4, o = (c & 15) * 8;
        size_t g = (size_t)(b * Ss + q0 + r) * Dd + h * HDd + o;
        *(uint4*)(sQh + r * FST + o) = *(const uint4*)(Qh + g);
        *(uint4*)(sQl + r * FST + o) = *(const uint4*)(Ql + g);
    }
    fl_load_kv(sm32 + 4 * FQE, tid, b, kvh, 0, Kh, Kl, Vh, Vl);
    CP_COMMIT();

    float m0 = -1e30f, m1 = -1e30f, l0 = 0.0f, l1 = 0.0f;
    float O[16][4];
#pragma unroll
    for (int i = 0; i < 16; i++) { O[i][0] = O[i][1] = O[i][2] = O[i][3] = 0.0f; }

    for (int kt = 0; kt <= qt; kt++) {
        const int stage = kt & 1;
        if (kt < qt) {
            fl_load_kv(sm32 + 4 * FQE + (stage ^ 1) * 8 * FQE, tid, b, kvh, (kt + 1) * 64,
                       Kh, Kl, Vh, Vl);
            CP_COMMIT();
            CP_WAIT1();
        } else {
            CP_WAIT0();
        }
        __syncthreads();

        const bf16* sKh = smb + 2 * FQE + stage * 4 * FQE;
        const bf16* sKl = sKh + FQE;
        const uint32_t vh32 = sm32 + (2 * FQE + stage * 4 * FQE + 2 * FQE) * 2;
        const uint32_t vl32 = vh32 + 2 * FQE;

        float S[8][4];
#pragma unroll
        for (int nt = 0; nt < 8; nt++) S[nt][0] = S[nt][1] = S[nt][2] = S[nt][3] = 0.0f;

#pragma unroll
        for (int kst = 0; kst < 8; kst++) {
            const int pp2 = kst * 16 + lc * 2;
            const int r0 = wrow + lr;
            uint32_t qa_h[4], qa_l[4];
            qa_h[0] = *(const uint32_t*)(sQh + r0 * FST + pp2);
            qa_h[1] = *(const uint32_t*)(sQh + (r0 + 8) * FST + pp2);
            qa_h[2] = *(const uint32_t*)(sQh + r0 * FST + pp2 + 8);
            qa_h[3] = *(const uint32_t*)(sQh + (r0 + 8) * FST + pp2 + 8);
            qa_l[0] = *(const uint32_t*)(sQl + r0 * FST + pp2);
            qa_l[1] = *(const uint32_t*)(sQl + (r0 + 8) * FST + pp2);
            qa_l[2] = *(const uint32_t*)(sQl + r0 * FST + pp2 + 8);
            qa_l[3] = *(const uint32_t*)(sQl + (r0 + 8) * FST + pp2 + 8);
#pragma unroll
            for (int nt = 0; nt < 8; nt++) {
                const int n0 = nt * 8 + lr;
                uint32_t kb[2], klb[2];
                kb[0]  = *(const uint32_t*)(sKh + n0 * FST + pp2);
                kb[1]  = *(const uint32_t*)(sKh + n0 * FST + pp2 + 8);
                klb[0] = *(const uint32_t*)(sKl + n0 * FST + pp2);
                klb[1] = *(const uint32_t*)(sKl + n0 * FST + pp2 + 8);
                mma16816(S[nt], qa_h, kb);
                mma16816(S[nt], qa_h, klb);
                mma16816(S[nt], qa_l, kb);
            }
        }

        if (kt == qt) {
            const int row0 = q0 + wrow + lr;
#pragma unroll
            for (int nt = 0; nt < 8; nt++) {
                const int col = kt * 64 + nt * 8 + lc * 2;
                if (col     > row0)     S[nt][0] = -1e30f;
                if (col + 1 > row0)     S[nt][1] = -1e30f;
                if (col     > row0 + 8) S[nt][2] = -1e30f;
                if (col + 1 > row0 + 8) S[nt][3] = -1e30f;
            }
        }

        float rm0 = -1e30f, rm1 = -1e30f;
#pragma unroll
        for (int nt = 0; nt < 8; nt++) {
            rm0 = fmaxf(rm0, fmaxf(S[nt][0], S[nt][1]));
            rm1 = fmaxf(rm1, fmaxf(S[nt][2], S[nt][3]));
        }
        rm0 = fmaxf(rm0, __shfl_xor_sync(0xffffffffu, rm0, 1));
        rm0 = fmaxf(rm0, __shfl_xor_sync(0xffffffffu, rm0, 2));
        rm1 = fmaxf(rm1, __shfl_xor_sync(0xffffffffu, rm1, 1));
        rm1 = fmaxf(rm1, __shfl_xor_sync(0xffffffffu, rm1, 2));
        float mn0 = fmaxf(m0, rm0), mn1 = fmaxf(m1, rm1);
        float a0 = __expf(m0 - mn0), a1 = __expf(m1 - mn1);
        float rs0 = 0.0f, rs1 = 0.0f;
#pragma unroll
        for (int nt = 0; nt < 8; nt++) {
            S[nt][0] = __expf(S[nt][0] - mn0);
            S[nt][1] = __expf(S[nt][1] - mn0);
            S[nt][2] = __expf(S[nt][2] - mn1);
            S[nt][3] = __expf(S[nt][3] - mn1);
            rs0 += S[nt][0] + S[nt][1];
            rs1 += S[nt][2] + S[nt][3];
        }
        rs0 += __shfl_xor_sync(0xffffffffu, rs0, 1);
        rs0 += __shfl_xor_sync(0xffffffffu, rs0, 2);
        rs1 += __shfl_xor_sync(0xffffffffu, rs1, 1);
        rs1 += __shfl_xor_sync(0xffffffffu, rs1, 2);
        l0 = l0 * a0 + rs0;
        l1 = l1 * a1 + rs1;
        m0 = mn0; m1 = mn1;
#pragma unroll
        for (int i = 0; i < 16; i++) {
            O[i][0] *= a0; O[i][1] *= a0; O[i][2] *= a1; O[i][3] *= a1;
        }

        uint32_t pa_h[4][4], pa_l[4][4];
#pragma unroll
        for (int ks = 0; ks < 4; ks++) {
            splitpk(S[2 * ks][0],     S[2 * ks][1],     pa_h[ks][0], pa_l[ks][0]);
            splitpk(S[2 * ks][2],     S[2 * ks][3],     pa_h[ks][1], pa_l[ks][1]);
            splitpk(S[2 * ks + 1][0], S[2 * ks + 1][1], pa_h[ks][2], pa_l[ks][2]);
            splitpk(S[2 * ks + 1][2], S[2 * ks + 1][3], pa_h[ks][3], pa_l[ks][3]);
        }

#pragma unroll
        for (int ks = 0; ks < 4; ks++) {
            const uint32_t va = ((uint32_t)(16 * ks + (lane & 15)) * FST) * 2 + (lane >> 4) * 16;
#pragma unroll
            for (int ntp = 0; ntp < 8; ntp++) {
                uint32_t vh4[4], vl4[4];
                LDSM4T(vh4, vh32 + va + ntp * 32);
                LDSM4T(vl4, vl32 + va + ntp * 32);
                uint32_t b0[2] = {vh4[0], vh4[1]}, b1[2] = {vh4[2], vh4[3]};
                uint32_t c0[2] = {vl4[0], vl4[1]}, c1[2] = {vl4[2], vl4[3]};
                mma16816(O[2 * ntp],     pa_h[ks], b0);
                mma16816(O[2 * ntp],     pa_l[ks], b0);
                mma16816(O[2 * ntp],     pa_h[ks], c0);
                mma16816(O[2 * ntp + 1], pa_h[ks], b1);
                mma16816(O[2 * ntp + 1], pa_l[ks], b1);
                mma16816(O[2 * ntp + 1], pa_h[ks], c1);
            }
        }
        __syncthreads();
    }

    // epilogue: normalize, store fp16 into Of
    float il0 = 1.0f / l0, il1 = 1.0f / l1;
    size_t r0 = (size_t)(b * Ss + q0 + wrow + lr) * Dd + h * HDd;
    size_t r1 = r0 + 8 * (size_t)Dd;
#pragma unroll
    for (int nt = 0; nt < 16; nt++) {
        int cc = nt * 8 + lc * 2;
        *(__half2*)(Of + r0 + cc) = __floats2half2_rn(O[nt][0] * il0, O[nt][1] * il0);
        *(__half2*)(Of + r1 + cc) = __floats2half2_rn(O[nt][2] * il1, O[nt][3] * il1);
    }
}

// ---------------- launch ----------------------------------------------------
extern "C" void kernel_launch(void* const* d_in, const int* in_sizes, int n_in,
                              void* d_out, int out_size) {
    const float* x    = (const float*)d_in[0];
    const float* Wq   = (const float*)d_in[1];
    const float* Wk   = (const float*)d_in[2];
    const float* Wv   = (const float*)d_in[3];
    const float* Wp   = (const float*)d_in[4];
    const float* gain = (const float*)d_in[5];
    float* out = (float*)d_out;

    float* qkv;
    bf16 *xh, *xl, *wh, *wl, *kh, *kl, *vh, *vl;
    __half *xf, *wf;
    cudaGetSymbolAddress((void**)&qkv, g_qkv);
    cudaGetSymbolAddress((void**)&xh, g_xh);
    cudaGetSymbolAddress((void**)&xl, g_xl);
    cudaGetSymbolAddress((void**)&wh, g_wh);
    cudaGetSymbolAddress((void**)&wl, g_wl);
    cudaGetSymbolAddress((void**)&kh, g_kh);
    cudaGetSymbolAddress((void**)&kl, g_kl);
    cudaGetSymbolAddress((void**)&vh, g_vh);
    cudaGetSymbolAddress((void**)&vl, g_vl);
    cudaGetSymbolAddress((void**)&xf, g_xf);
    cudaGetSymbolAddress((void**)&wf, g_wf);

    cudaFuncSetAttribute(gemm_bf16s, cudaFuncAttributeMaxDynamicSharedMemorySize, GEMM_SMEM);
    cudaFuncSetAttribute(gemm_fp16s, cudaFuncAttributeMaxDynamicSharedMemorySize, GEMM2_SMEM);
    cudaFuncSetAttribute(flash2,     cudaFuncAttributeMaxDynamicSharedMemorySize, FL2_SMEM);

    const int M = Bb * Ss;                 // 4096
    const int n4x = M * Dd / 4;
    const int n4w = Dd * Dd / 4;
    const int n4k = 512 * Dd / 4;

    rope_table_kernel<<<(Ss * 64 + 255) / 256, 256>>>();

    // x: bf16 split (precise QK path) + fp16 (V path)
    cvt_split<<<(n4x + 255) / 256, 256>>>(x, xh, xl, n4x);
    cvt_half<<<(n4x + 255) / 256, 256>>>(x, xf, n4x);

    // fused [Wq;Wk] split weights: rows 0-2047 Wq, 2048-2559 Wk
    cvt_split<<<(n4w + 255) / 256, 256>>>(Wq, wh, wl, n4w);
    cvt_split<<<(n4k + 255) / 256, 256>>>(Wk, wh + (size_t)2048 * Dd, wl + (size_t)2048 * Dd, n4k);
    // Wv as fp16
    cvt_half<<<(n4k + 255) / 256, 256>>>(Wv, wf, n4k);

    // qk: precise 3-term bf16; v: 1-term fp16. Both into g_qkv (ldc=3072).
    gemm_bf16s<<<dim3(NQK / 128, M / 128), 256, GEMM_SMEM>>>(xh, xl, wh, wl, qkv, M, NQK, Dd, NQKV);
    gemm_fp16s<<<dim3(512 / 128, M / 128), 256, GEMM2_SMEM>>>(xf, wf, qkv + 2560, M, 512, Dd, NQKV);

    q_post<<<(Bb * Ss * Hh) / 8, 256>>>(gain, xh, xl);
    kv_post<<<(Bb * Ss * KVHh) / 8, 256>>>(kh, kl, vh, vl);

    // flash: reads Q split from xh/xl, writes fp16 attn-out into xf
    flash2<<<dim3(Ss / 64, Hh, Bb), 128, FL2_SMEM>>>(xh, xl, kh, kl, vh, vl, xf);

    // out-proj: fp16 1-term
    cvt_half<<<(n4w + 255) / 256, 256>>>(Wp, wf, n4w);
    gemm_fp16s<<<dim3(Dd / 128, M / 128), 256, GEMM2_SMEM>>>(xf, wf, out, M, Dd, Dd, Dd);
}

// round 16
// speedup vs baseline: 1.4681x; 1.1053x over previous
#include <cuda_runtime.h>
#include <cuda_bf16.h>
#include <cuda_fp16.h>
#include <math.h>
#include <stdint.h>

#define Bb   2
#define Ss   2048
#define Dd   2048
#define Hh   16
#define KVHh 4
#define HDd  128
#define NQKV 3072      // col layout in g_qkv: 0-2047 q, 2048-2559 k, 2560-3071 v
#define NQK  2560

typedef __nv_bfloat16 bf16;

// ---------------- scratch (static device globals; no allocs) ----------------
__device__ float g_qkv[Bb * Ss * NQKV];
__device__ float g_cos[Ss * 64];
__device__ float g_sin[Ss * 64];
// bf16 split operands (precise path)
__device__ __align__(16) bf16 g_xh[Bb * Ss * Dd];
__device__ __align__(16) bf16 g_xl[Bb * Ss * Dd];
__device__ __align__(16) bf16 g_wh[NQK * Dd];
__device__ __align__(16) bf16 g_wl[NQK * Dd];
__device__ __align__(16) bf16 g_kh[Bb * Ss * KVHh * HDd];
__device__ __align__(16) bf16 g_kl[Bb * Ss * KVHh * HDd];
// fp16 operands (linear paths)
__device__ __align__(16) __half g_vf[Bb * Ss * KVHh * HDd];
__device__ __align__(16) __half g_xf[Bb * Ss * Dd];   // x-fp16, then attn-out-fp16
__device__ __align__(16) __half g_wf[Dd * Dd];

// ---------------- helpers ----------------------------------------------------
__device__ __forceinline__ uint32_t smem_u32(const void* p) {
    uint32_t a;
    asm("{ .reg .u64 t; cvta.to.shared.u64 t, %1; cvt.u32.u64 %0, t; }" : "=r"(a) : "l"(p));
    return a;
}
#define CP_ASYNC16(dst, src) \
    asm volatile("cp.async.cg.shared.global [%0], [%1], 16;" :: "r"(dst), "l"(src) : "memory")
#define CP_COMMIT()  asm volatile("cp.async.commit_group;" ::: "memory")
#define CP_WAIT1()   asm volatile("cp.async.wait_group 1;" ::: "memory")
#define CP_WAIT0()   asm volatile("cp.async.wait_group 0;" ::: "memory")

__device__ __forceinline__ void mma16816(float* d, const uint32_t* a, const uint32_t* b) {
    asm volatile("mma.sync.aligned.m16n8k16.row.col.f32.bf16.bf16.f32 "
        "{%0,%1,%2,%3}, {%4,%5,%6,%7}, {%8,%9}, {%0,%1,%2,%3};"
        : "+f"(d[0]), "+f"(d[1]), "+f"(d[2]), "+f"(d[3])
        : "r"(a[0]), "r"(a[1]), "r"(a[2]), "r"(a[3]), "r"(b[0]), "r"(b[1]));
}
__device__ __forceinline__ void mma16816h(float* d, const uint32_t* a, const uint32_t* b) {
    asm volatile("mma.sync.aligned.m16n8k16.row.col.f32.f16.f16.f32 "
        "{%0,%1,%2,%3}, {%4,%5,%6,%7}, {%8,%9}, {%0,%1,%2,%3};"
        : "+f"(d[0]), "+f"(d[1]), "+f"(d[2]), "+f"(d[3])
        : "r"(a[0]), "r"(a[1]), "r"(a[2]), "r"(a[3]), "r"(b[0]), "r"(b[1]));
}
#define LDSM4T(r, a) \
    asm volatile("ldmatrix.sync.aligned.m8n8.x4.trans.shared.b16 {%0,%1,%2,%3}, [%4];" \
        : "=r"((r)[0]), "=r"((r)[1]), "=r"((r)[2]), "=r"((r)[3]) : "r"(a))

// pack two fp32 into bf16x2 (hi) and their residuals into bf16x2 (lo)
__device__ __forceinline__ void splitpk(float x0, float x1, uint32_t& hi, uint32_t& lo) {
    bf16 h0 = __float2bfloat16(x0), h1 = __float2bfloat16(x1);
    __nv_bfloat162 th = __halves2bfloat162(h0, h1);
    hi = *(uint32_t*)&th;
    bf16 r0 = __float2bfloat16(x0 - __bfloat162float(h0));
    bf16 r1 = __float2bfloat16(x1 - __bfloat162float(h1));
    __nv_bfloat162 tl = __halves2bfloat162(r0, r1);
    lo = *(uint32_t*)&tl;
}
__device__ __forceinline__ uint32_t packh2(float x0, float x1) {
    __half2 h = __floats2half2_rn(x0, x1);
    return *(uint32_t*)&h;
}

// ---------------- RoPE table ------------------------------------------------
__global__ void rope_table_kernel() {
    int i = blockIdx.x * blockDim.x + threadIdx.x;
    if (i >= Ss * 64) return;
    int s = i >> 6, j = i & 63;
    float e   = (float)(2 * j) / (float)HDd;
    float inv = 1.0f / powf(10000.0f, e);
    float ang = (float)s * inv;
    g_cos[i] = (float)cos((double)ang);
    g_sin[i] = (float)sin((double)ang);
}

// ---------------- fp32 -> bf16 hi/lo split ----------------------------------
__global__ __launch_bounds__(256) void cvt_split(const float* __restrict__ src,
                                                 bf16* __restrict__ hi,
                                                 bf16* __restrict__ lo, int n4) {
    int i = blockIdx.x * blockDim.x + threadIdx.x;
    if (i >= n4) return;
    float4 v = ((const float4*)src)[i];
    uint32_t h0, l0, h1, l1;
    splitpk(v.x, v.y, h0, l0);
    splitpk(v.z, v.w, h1, l1);
    ((uint32_t*)hi)[2 * i] = h0; ((uint32_t*)hi)[2 * i + 1] = h1;
    ((uint32_t*)lo)[2 * i] = l0; ((uint32_t*)lo)[2 * i + 1] = l1;
}

// ---------------- fp32 -> fp16 ----------------------------------------------
__global__ __launch_bounds__(256) void cvt_half(const float* __restrict__ src,
                                                __half* __restrict__ dst, int n4) {
    int i = blockIdx.x * blockDim.x + threadIdx.x;
    if (i >= n4) return;
    float4 v = ((const float4*)src)[i];
    ((__half2*)dst)[2 * i]     = __floats2half2_rn(v.x, v.y);
    ((__half2*)dst)[2 * i + 1] = __floats2half2_rn(v.z, v.w);
}

// ---------------- split-bf16 HMMA GEMM (R14-proven) -------------------------
#define LDA        40
#define ARRB       (128 * LDA * 2)
#define STAGEB     (4 * ARRB)
#define GEMM_SMEM  (2 * STAGEB)

__device__ __forceinline__ void gemm_load_chunk(
    uint32_t sm32, int buf, int tid, int c,
    const bf16* __restrict__ Ah, const bf16* __restrict__ Al,
    const bf16* __restrict__ Bh, const bf16* __restrict__ Bl,
    int bm, int bn, int K) {
    int row = tid >> 2;
    int t16 = tid & 3;
    uint32_t so = sm32 + buf * STAGEB + (uint32_t)row * 80 + (uint32_t)t16 * 16;
    size_t gA = (size_t)(bm + row) * K + (size_t)c * 32 + t16 * 8;
    size_t gB = (size_t)(bn + row) * K + (size_t)c * 32 + t16 * 8;
    size_t stp = (size_t)64 * K;
    CP_ASYNC16(so,                       Ah + gA);
    CP_ASYNC16(so + 64 * 80,             Ah + gA + stp);
    CP_ASYNC16(so + ARRB,                Al + gA);
    CP_ASYNC16(so + ARRB + 64 * 80,      Al + gA + stp);
    CP_ASYNC16(so + 2 * ARRB,            Bh + gB);
    CP_ASYNC16(so + 2 * ARRB + 64 * 80,  Bh + gB + stp);
    CP_ASYNC16(so + 3 * ARRB,            Bl + gB);
    CP_ASYNC16(so + 3 * ARRB + 64 * 80,  Bl + gB + stp);
}

__global__ __launch_bounds__(256) void gemm_bf16s(
    const bf16* __restrict__ Ah, const bf16* __restrict__ Al,
    const bf16* __restrict__ Bh, const bf16* __restrict__ Bl,
    float* __restrict__ C, int M, int N, int K, int ldc) {
    extern __shared__ char sm[];
    const uint32_t sm32 = smem_u32(sm);
    const int tid  = threadIdx.x;
    const int wid  = tid >> 5, lane = tid & 31;
    const int lr   = lane >> 2, lc = lane & 3;
    const int wm   = wid & 1;
    const int wn   = wid >> 1;
    const int bm = blockIdx.y * 128, bn = blockIdx.x * 128;

    float acc[4][4][4];
#pragma unroll
    for (int i = 0; i < 4; i++)
#pragma unroll
        for (int j = 0; j < 4; j++)
#pragma unroll
            for (int r = 0; r < 4; r++) acc[i][j][r] = 0.0f;

    const int NC = K >> 5;
    gemm_load_chunk(sm32, 0, tid, 0, Ah, Al, Bh, Bl, bm, bn, K);
    CP_COMMIT();

    for (int c = 0; c < NC; c++) {
        const int buf = c & 1;
        if (c + 1 < NC) {
            gemm_load_chunk(sm32, buf ^ 1, tid, c + 1, Ah, Al, Bh, Bl, bm, bn, K);
            CP_COMMIT();
            CP_WAIT1();
        } else {
            CP_WAIT0();
        }
        __syncthreads();

        const bf16* sA  = (const bf16*)(sm + buf * STAGEB);
        const bf16* sAl = sA + 128 * LDA;
        const bf16* sB  = sA + 2 * 128 * LDA;
        const bf16* sBl = sA + 3 * 128 * LDA;
#pragma unroll
        for (int kst = 0; kst < 2; kst++) {
            const int pp = kst * 8 + lc;
            uint32_t ah[4][4], al[4][4], bh[4][2], bl[4][2];
#pragma unroll
            for (int mt = 0; mt < 4; mt++) {
                int r0 = wm * 64 + mt * 16 + lr;
                ah[mt][0] = *(const uint32_t*)(sA + r0 * LDA + pp * 2);
                ah[mt][1] = *(const uint32_t*)(sA + (r0 + 8) * LDA + pp * 2);
                ah[mt][2] = *(const uint32_t*)(sA + r0 * LDA + (pp + 4) * 2);
                ah[mt][3] = *(const uint32_t*)(sA + (r0 + 8) * LDA + (pp + 4) * 2);
                al[mt][0] = *(const uint32_t*)(sAl + r0 * LDA + pp * 2);
                al[mt][1] = *(const uint32_t*)(sAl + (r0 + 8) * LDA + pp * 2);
                al[mt][2] = *(const uint32_t*)(sAl + r0 * LDA + (pp + 4) * 2);
                al[mt][3] = *(const uint32_t*)(sAl + (r0 + 8) * LDA + (pp + 4) * 2);
            }
#pragma unroll
            for (int nt = 0; nt < 4; nt++) {
                int n0 = wn * 32 + nt * 8 + lr;
                bh[nt][0] = *(const uint32_t*)(sB + n0 * LDA + pp * 2);
                bh[nt][1] = *(const uint32_t*)(sB + n0 * LDA + (pp + 4) * 2);
                bl[nt][0] = *(const uint32_t*)(sBl + n0 * LDA + pp * 2);
                bl[nt][1] = *(const uint32_t*)(sBl + n0 * LDA + (pp + 4) * 2);
            }
#pragma unroll
            for (int mt = 0; mt < 4; mt++)
#pragma unroll
                for (int nt = 0; nt < 4; nt++)
                    mma16816(acc[mt][nt], ah[mt], bh[nt]);
#pragma unroll
            for (int mt = 0; mt < 4; mt++)
#pragma unroll
                for (int nt = 0; nt < 4; nt++)
                    mma16816(acc[mt][nt], ah[mt], bl[nt]);
#pragma unroll
            for (int mt = 0; mt < 4; mt++)
#pragma unroll
                for (int nt = 0; nt < 4; nt++)
                    mma16816(acc[mt][nt], al[mt], bh[nt]);
        }
        __syncthreads();
    }

#pragma unroll
    for (int mt = 0; mt < 4; mt++) {
        int m = bm + wm * 64 + mt * 16 + lr;
#pragma unroll
        for (int nt = 0; nt < 4; nt++) {
            int n = bn + wn * 32 + nt * 8 + lc * 2;
            *(float2*)(C + (size_t)m * ldc + n)       = make_float2(acc[mt][nt][0], acc[mt][nt][1]);
            *(float2*)(C + (size_t)(m + 8) * ldc + n) = make_float2(acc[mt][nt][2], acc[mt][nt][3]);
        }
    }
}

// ---------------- plain fp16 HMMA GEMM (1-term, linear paths) ----------------
#define ARRB2       (128 * LDA * 2)
#define STAGE2      (2 * ARRB2)
#define GEMM2_SMEM  (2 * STAGE2)

__device__ __forceinline__ void gemm16_load(
    uint32_t sm32, int buf, int tid, int c,
    const __half* __restrict__ A, const __half* __restrict__ B,
    int bm, int bn, int K) {
    int row = tid >> 2;
    int t16 = tid & 3;
    uint32_t so = sm32 + buf * STAGE2 + (uint32_t)row * 80 + (uint32_t)t16 * 16;
    size_t gA = (size_t)(bm + row) * K + (size_t)c * 32 + t16 * 8;
    size_t gB = (size_t)(bn + row) * K + (size_t)c * 32 + t16 * 8;
    size_t stp = (size_t)64 * K;
    CP_ASYNC16(so,                   A + gA);
    CP_ASYNC16(so + 64 * 80,         A + gA + stp);
    CP_ASYNC16(so + ARRB2,           B + gB);
    CP_ASYNC16(so + ARRB2 + 64 * 80, B + gB + stp);
}

__global__ __launch_bounds__(256) void gemm_fp16s(
    const __half* __restrict__ A, const __half* __restrict__ B,
    float* __restrict__ C, int M, int N, int K, int ldc) {
    extern __shared__ char sm[];
    const uint32_t sm32 = smem_u32(sm);
    const int tid  = threadIdx.x;
    const int wid  = tid >> 5, lane = tid & 31;
    const int lr   = lane >> 2, lc = lane & 3;
    const int wm   = wid & 1;
    const int wn   = wid >> 1;
    const int bm = blockIdx.y * 128, bn = blockIdx.x * 128;

    float acc[4][4][4];
#pragma unroll
    for (int i = 0; i < 4; i++)
#pragma unroll
        for (int j = 0; j < 4; j++)
#pragma unroll
            for (int r = 0; r < 4; r++) acc[i][j][r] = 0.0f;

    const int NC = K >> 5;
    gemm16_load(sm32, 0, tid, 0, A, B, bm, bn, K);
    CP_COMMIT();

    for (int c = 0; c < NC; c++) {
        const int buf = c & 1;
        if (c + 1 < NC) {
            gemm16_load(sm32, buf ^ 1, tid, c + 1, A, B, bm, bn, K);
            CP_COMMIT();
            CP_WAIT1();
        } else {
            CP_WAIT0();
        }
        __syncthreads();

        const __half* sA = (const __half*)(sm + buf * STAGE2);
        const __half* sB = sA + 128 * LDA;
#pragma unroll
        for (int kst = 0; kst < 2; kst++) {
            const int pp = kst * 8 + lc;
            uint32_t ah[4][4], bh[4][2];
#pragma unroll
            for (int mt = 0; mt < 4; mt++) {
                int r0 = wm * 64 + mt * 16 + lr;
                ah[mt][0] = *(const uint32_t*)(sA + r0 * LDA + pp * 2);
                ah[mt][1] = *(const uint32_t*)(sA + (r0 + 8) * LDA + pp * 2);
                ah[mt][2] = *(const uint32_t*)(sA + r0 * LDA + (pp + 4) * 2);
                ah[mt][3] = *(const uint32_t*)(sA + (r0 + 8) * LDA + (pp + 4) * 2);
            }
#pragma unroll
            for (int nt = 0; nt < 4; nt++) {
                int n0 = wn * 32 + nt * 8 + lr;
                bh[nt][0] = *(const uint32_t*)(sB + n0 * LDA + pp * 2);
                bh[nt][1] = *(const uint32_t*)(sB + n0 * LDA + (pp + 4) * 2);
            }
#pragma unroll
            for (int mt = 0; mt < 4; mt++)
#pragma unroll
                for (int nt = 0; nt < 4; nt++)
                    mma16816h(acc[mt][nt], ah[mt], bh[nt]);
        }
        __syncthreads();
    }

#pragma unroll
    for (int mt = 0; mt < 4; mt++) {
        int m = bm + wm * 64 + mt * 16 + lr;
#pragma unroll
        for (int nt = 0; nt < 4; nt++) {
            int n = bn + wn * 32 + nt * 8 + lc * 2;
            *(float2*)(C + (size_t)m * ldc + n)       = make_float2(acc[mt][nt][0], acc[mt][nt][1]);
            *(float2*)(C + (size_t)(m + 8) * ldc + n) = make_float2(acc[mt][nt][2], acc[mt][nt][3]);
        }
    }
}

// ---------------- q/kv epilogues --------------------------------------------
__global__ __launch_bounds__(256) void q_post(const float* __restrict__ gain,
                                              bf16* __restrict__ qh, bf16* __restrict__ ql) {
    int wid  = blockIdx.x * 8 + (threadIdx.x >> 5);
    int lane = threadIdx.x & 31;
    int h = wid & (Hh - 1);
    int row = wid >> 4;
    int s = row & (Ss - 1);
    const float* base = g_qkv + (size_t)row * NQKV + h * HDd;
    float e0 = base[lane], e1 = base[lane + 32], e2 = base[lane + 64], e3 = base[lane + 96];
    float ssum = e0 * e0 + e1 * e1 + e2 * e2 + e3 * e3;
#pragma unroll
    for (int o = 16; o > 0; o >>= 1) ssum += __shfl_xor_sync(0xffffffffu, ssum, o);
    float r = rsqrtf(ssum * (1.0f / 128.0f) + 1e-6f);
    float g = gain[h] * r * 0.08838834764831845f;
    float c0 = g_cos[s * 64 + lane],      sn0 = g_sin[s * 64 + lane];
    float c1 = g_cos[s * 64 + lane + 32], sn1 = g_sin[s * 64 + lane + 32];
    float o0 = ( e0 * c0  + e2 * sn0) * g;
    float o1 = ( e1 * c1  + e3 * sn1) * g;
    float o2 = (-e0 * sn0 + e2 * c0 ) * g;
    float o3 = (-e1 * sn1 + e3 * c1 ) * g;
    size_t off = (size_t)wid * 128;
    bf16 h0 = __float2bfloat16(o0); qh[off + lane]      = h0; ql[off + lane]      = __float2bfloat16(o0 - __bfloat162float(h0));
    bf16 h1 = __float2bfloat16(o1); qh[off + lane + 32] = h1; ql[off + lane + 32] = __float2bfloat16(o1 - __bfloat162float(h1));
    bf16 h2 = __float2bfloat16(o2); qh[off + lane + 64] = h2; ql[off + lane + 64] = __float2bfloat16(o2 - __bfloat162float(h2));
    bf16 h3 = __float2bfloat16(o3); qh[off + lane + 96] = h3; ql[off + lane + 96] = __float2bfloat16(o3 - __bfloat162float(h3));
}

__global__ __launch_bounds__(256) void kv_post(bf16* __restrict__ kh, bf16* __restrict__ kl,
                                               __half* __restrict__ vf) {
    int wid  = blockIdx.x * 8 + (threadIdx.x >> 5);
    int lane = threadIdx.x & 31;
    int kvh = wid & 3;
    int row = wid >> 2;
    int s = row & (Ss - 1);
    const float* kb = g_qkv + (size_t)row * NQKV + 2048 + kvh * HDd;
    const float* vb = kb + 512;
    float e0 = kb[lane], e1 = kb[lane + 32], e2 = kb[lane + 64], e3 = kb[lane + 96];
    float ssum = e0 * e0 + e1 * e1 + e2 * e2 + e3 * e3;
#pragma unroll
    for (int o = 16; o > 0; o >>= 1) ssum += __shfl_xor_sync(0xffffffffu, ssum, o);
    float r = rsqrtf(ssum * (1.0f / 128.0f) + 1e-6f);
    float c0 = g_cos[s * 64 + lane],      sn0 = g_sin[s * 64 + lane];
    float c1 = g_cos[s * 64 + lane + 32], sn1 = g_sin[s * 64 + lane + 32];
    float o0 = ( e0 * c0  + e2 * sn0) * r;
    float o1 = ( e1 * c1  + e3 * sn1) * r;
    float o2 = (-e0 * sn0 + e2 * c0 ) * r;
    float o3 = (-e1 * sn1 + e3 * c1 ) * r;
    size_t off = (size_t)wid * 128;
    bf16 h0 = __float2bfloat16(o0); kh[off + lane]      = h0; kl[off + lane]      = __float2bfloat16(o0 - __bfloat162float(h0));
    bf16 h1 = __float2bfloat16(o1); kh[off + lane + 32] = h1; kl[off + lane + 32] = __float2bfloat16(o1 - __bfloat162float(h1));
    bf16 h2 = __float2bfloat16(o2); kh[off + lane + 64] = h2; kl[off + lane + 64] = __float2bfloat16(o2 - __bfloat162float(h2));
    bf16 h3 = __float2bfloat16(o3); kh[off + lane + 96] = h3; kl[off + lane + 96] = __float2bfloat16(o3 - __bfloat162float(h3));
    // v: fp16 copy
#pragma unroll
    for (int j = 0; j < 4; j++)
        vf[off + lane + 32 * j] = __float2half_rn(vb[lane + 32 * j]);
}

// ---------------- HMMA flash attention: S 3-term bf16, PV 1-term fp16 -------
// smem per stage: Kh, Kl (bf16 split) + Vf (fp16). Q resident bf16 split.
#define FST 136
#define FQE (64 * FST)                      // elems per array; bytes = 2*FQE
#define FL2_SMEM (16 * FQE)                 // (2 Q + 2*3 stage arrays) * 2FQE bytes

__device__ __forceinline__ void fl_load_kv(uint32_t sbase, int tid, int b, int kvh, int k0,
    const bf16* __restrict__ Kh, const bf16* __restrict__ Kl,
    const __half* __restrict__ Vf) {
#pragma unroll
    for (int it = 0; it < 8; it++) {
        int c = tid + it * 128;
        int r = c >> 4, o16 = c & 15;
        uint32_t d = sbase + (uint32_t)r * (FST * 2) + o16 * 16;
        size_t g = ((size_t)((b * Ss + k0 + r) * KVHh + kvh)) * HDd + o16 * 8;
        CP_ASYNC16(d,               Kh + g);
        CP_ASYNC16(d + 2 * FQE,     Kl + g);
        CP_ASYNC16(d + 4 * FQE,     Vf + g);
    }
}

__global__ __launch_bounds__(128) void flash2(
    const bf16* __restrict__ Qh, const bf16* __restrict__ Ql,
    const bf16* __restrict__ Kh, const bf16* __restrict__ Kl,
    const __half* __restrict__ Vf,
    __half* __restrict__ Of) {
    extern __shared__ bf16 smb[];
    bf16* sQh = smb;
    bf16* sQl = smb + FQE;
    const uint32_t sm32 = smem_u32(smb);
    const int tid = threadIdx.x, wid = tid >> 5, lane = tid & 31;
    const int lr = lane >> 2, lc = lane & 3;
    const int qt = (Ss / 64 - 1) - blockIdx.x;
    const int h = blockIdx.y, b = blockIdx.z, kvh = h >> 2;
    const int q0 = qt * 64;
    const int wrow = wid * 16;

#pragma unroll
    for (int it = 0; it < 8; it++) {
        int c = tid + it * 128;
        int r = c >> 4, o = (c & 15) * 8;
        size_t g = (size_t)(b * Ss + q0 + r) * Dd + h * HDd + o;
        *(uint4*)(sQh + r * FST + o) = *(const uint4*)(Qh + g);
        *(uint4*)(sQl + r * FST + o) = *(const uint4*)(Ql + g);
    }
    fl_load_kv(sm32 + 4 * FQE, tid, b, kvh, 0, Kh, Kl, Vf);
    CP_COMMIT();

    float m0 = -1e30f, m1 = -1e30f, l0 = 0.0f, l1 = 0.0f;
    float O[16][4];
#pragma unroll
    for (int i = 0; i < 16; i++) { O[i][0] = O[i][1] = O[i][2] = O[i][3] = 0.0f; }

    for (int kt = 0; kt <= qt; kt++) {
        const int stage = kt & 1;
        if (kt < qt) {
            fl_load_kv(sm32 + 4 * FQE + (stage ^ 1) * 6 * FQE, tid, b, kvh, (kt + 1) * 64,
                       Kh, Kl, Vf);
            CP_COMMIT();
            CP_WAIT1();
        } else {
            CP_WAIT0();
        }
        __syncthreads();

        const uint32_t kbase = sm32 + 4 * FQE + stage * 6 * FQE;   // bytes
        const bf16* sKh = (const bf16*)((char*)smb + (2 * FQE + stage * 3 * FQE) * 2);
        const bf16* sKl = sKh + FQE;
        const uint32_t vf32 = kbase + 4 * FQE;

        float S[8][4];
#pragma unroll
        for (int nt = 0; nt < 8; nt++) S[nt][0] = S[nt][1] = S[nt][2] = S[nt][3] = 0.0f;

#pragma unroll
        for (int kst = 0; kst < 8; kst++) {
            const int pp2 = kst * 16 + lc * 2;
            const int r0 = wrow + lr;
            uint32_t qa_h[4], qa_l[4];
            qa_h[0] = *(const uint32_t*)(sQh + r0 * FST + pp2);
            qa_h[1] = *(const uint32_t*)(sQh + (r0 + 8) * FST + pp2);
            qa_h[2] = *(const uint32_t*)(sQh + r0 * FST + pp2 + 8);
            qa_h[3] = *(const uint32_t*)(sQh + (r0 + 8) * FST + pp2 + 8);
            qa_l[0] = *(const uint32_t*)(sQl + r0 * FST + pp2);
            qa_l[1] = *(const uint32_t*)(sQl + (r0 + 8) * FST + pp2);
            qa_l[2] = *(const uint32_t*)(sQl + r0 * FST + pp2 + 8);
            qa_l[3] = *(const uint32_t*)(sQl + (r0 + 8) * FST + pp2 + 8);
#pragma unroll
            for (int nt = 0; nt < 8; nt++) {
                const int n0 = nt * 8 + lr;
                uint32_t kb[2], klb[2];
                kb[0]  = *(const uint32_t*)(sKh + n0 * FST + pp2);
                kb[1]  = *(const uint32_t*)(sKh + n0 * FST + pp2 + 8);
                klb[0] = *(const uint32_t*)(sKl + n0 * FST + pp2);
                klb[1] = *(const uint32_t*)(sKl + n0 * FST + pp2 + 8);
                mma16816(S[nt], qa_h, kb);
                mma16816(S[nt], qa_h, klb);
                mma16816(S[nt], qa_l, kb);
            }
        }

        if (kt == qt) {
            const int row0 = q0 + wrow + lr;
#pragma unroll
            for (int nt = 0; nt < 8; nt++) {
                const int col = kt * 64 + nt * 8 + lc * 2;
                if (col     > row0)     S[nt][0] = -1e30f;
                if (col + 1 > row0)     S[nt][1] = -1e30f;
                if (col     > row0 + 8) S[nt][2] = -1e30f;
                if (col + 1 > row0 + 8) S[nt][3] = -1e30f;
            }
        }

        float rm0 = -1e30f, rm1 = -1e30f;
#pragma unroll
        for (int nt = 0; nt < 8; nt++) {
            rm0 = fmaxf(rm0, fmaxf(S[nt][0], S[nt][1]));
            rm1 = fmaxf(rm1, fmaxf(S[nt][2], S[nt][3]));
        }
        rm0 = fmaxf(rm0, __shfl_xor_sync(0xffffffffu, rm0, 1));
        rm0 = fmaxf(rm0, __shfl_xor_sync(0xffffffffu, rm0, 2));
        rm1 = fmaxf(rm1, __shfl_xor_sync(0xffffffffu, rm1, 1));
        rm1 = fmaxf(rm1, __shfl_xor_sync(0xffffffffu, rm1, 2));
        float mn0 = fmaxf(m0, rm0), mn1 = fmaxf(m1, rm1);
        float a0 = __expf(m0 - mn0), a1 = __expf(m1 - mn1);
        float rs0 = 0.0f, rs1 = 0.0f;
#pragma unroll
        for (int nt = 0; nt < 8; nt++) {
            S[nt][0] = __expf(S[nt][0] - mn0);
            S[nt][1] = __expf(S[nt][1] - mn0);
            S[nt][2] = __expf(S[nt][2] - mn1);
            S[nt][3] = __expf(S[nt][3] - mn1);
            rs0 += S[nt][0] + S[nt][1];
            rs1 += S[nt][2] + S[nt][3];
        }
        rs0 += __shfl_xor_sync(0xffffffffu, rs0, 1);
        rs0 += __shfl_xor_sync(0xffffffffu, rs0, 2);
        rs1 += __shfl_xor_sync(0xffffffffu, rs1, 1);
        rs1 += __shfl_xor_sync(0xffffffffu, rs1, 2);
        l0 = l0 * a0 + rs0;
        l1 = l1 * a1 + rs1;
        m0 = mn0; m1 = mn1;
#pragma unroll
        for (int i = 0; i < 16; i++) {
            O[i][0] *= a0; O[i][1] *= a0; O[i][2] *= a1; O[i][3] *= a1;
        }

        // P -> fp16 a-frags (1-term)
        uint32_t pf[4][4];
#pragma unroll
        for (int ks = 0; ks < 4; ks++) {
            pf[ks][0] = packh2(S[2 * ks][0],     S[2 * ks][1]);
            pf[ks][1] = packh2(S[2 * ks][2],     S[2 * ks][3]);
            pf[ks][2] = packh2(S[2 * ks + 1][0], S[2 * ks + 1][1]);
            pf[ks][3] = packh2(S[2 * ks + 1][2], S[2 * ks + 1][3]);
        }

        // O += P . V  (fp16 1-term)
#pragma unroll
        for (int ks = 0; ks < 4; ks++) {
            const uint32_t va = ((uint32_t)(16 * ks + (lane & 15)) * FST) * 2 + (lane >> 4) * 16;
#pragma unroll
            for (int ntp = 0; ntp < 8; ntp++) {
                uint32_t v4[4];
                LDSM4T(v4, vf32 + va + ntp * 32);
                uint32_t b0[2] = {v4[0], v4[1]}, b1[2] = {v4[2], v4[3]};
                mma16816h(O[2 * ntp],     pf[ks], b0);
                mma16816h(O[2 * ntp + 1], pf[ks], b1);
            }
        }
        __syncthreads();
    }

    float il0 = 1.0f / l0, il1 = 1.0f / l1;
    size_t r0 = (size_t)(b * Ss + q0 + wrow + lr) * Dd + h * HDd;
    size_t r1 = r0 + 8 * (size_t)Dd;
#pragma unroll
    for (int nt = 0; nt < 16; nt++) {
        int cc = nt * 8 + lc * 2;
        *(__half2*)(Of + r0 + cc) = __floats2half2_rn(O[nt][0] * il0, O[nt][1] * il0);
        *(__half2*)(Of + r1 + cc) = __floats2half2_rn(O[nt][2] * il1, O[nt][3] * il1);
    }
}

// ---------------- launch ----------------------------------------------------
extern "C" void kernel_launch(void* const* d_in, const int* in_sizes, int n_in,
                              void* d_out, int out_size) {
    const float* x    = (const float*)d_in[0];
    const float* Wq   = (const float*)d_in[1];
    const float* Wk   = (const float*)d_in[2];
    const float* Wv   = (const float*)d_in[3];
    const float* Wp   = (const float*)d_in[4];
    const float* gain = (const float*)d_in[5];
    float* out = (float*)d_out;

    float* qkv;
    bf16 *xh, *xl, *wh, *wl, *kh, *kl;
    __half *vf, *xf, *wf;
    cudaGetSymbolAddress((void**)&qkv, g_qkv);
    cudaGetSymbolAddress((void**)&xh, g_xh);
    cudaGetSymbolAddress((void**)&xl, g_xl);
    cudaGetSymbolAddress((void**)&wh, g_wh);
    cudaGetSymbolAddress((void**)&wl, g_wl);
    cudaGetSymbolAddress((void**)&kh, g_kh);
    cudaGetSymbolAddress((void**)&kl, g_kl);
    cudaGetSymbolAddress((void**)&vf, g_vf);
    cudaGetSymbolAddress((void**)&xf, g_xf);
    cudaGetSymbolAddress((void**)&wf, g_wf);

    cudaFuncSetAttribute(gemm_bf16s, cudaFuncAttributeMaxDynamicSharedMemorySize, GEMM_SMEM);
    cudaFuncSetAttribute(gemm_fp16s, cudaFuncAttributeMaxDynamicSharedMemorySize, GEMM2_SMEM);
    cudaFuncSetAttribute(flash2,     cudaFuncAttributeMaxDynamicSharedMemorySize, FL2_SMEM);

    const int M = Bb * Ss;                 // 4096
    const int n4x = M * Dd / 4;
    const int n4w = Dd * Dd / 4;
    const int n4k = 512 * Dd / 4;

    rope_table_kernel<<<(Ss * 64 + 255) / 256, 256>>>();

    cvt_split<<<(n4x + 255) / 256, 256>>>(x, xh, xl, n4x);
    cvt_half<<<(n4x + 255) / 256, 256>>>(x, xf, n4x);

    cvt_split<<<(n4w + 255) / 256, 256>>>(Wq, wh, wl, n4w);
    cvt_split<<<(n4k + 255) / 256, 256>>>(Wk, wh + (size_t)2048 * Dd, wl + (size_t)2048 * Dd, n4k);
    cvt_half<<<(n4k + 255) / 256, 256>>>(Wv, wf, n4k);

    gemm_bf16s<<<dim3(NQK / 128, M / 128), 256, GEMM_SMEM>>>(xh, xl, wh, wl, qkv, M, NQK, Dd, NQKV);
    gemm_fp16s<<<dim3(512 / 128, M / 128), 256, GEMM2_SMEM>>>(xf, wf, qkv + 2560, M, 512, Dd, NQKV);

    q_post<<<(Bb * Ss * Hh) / 8, 256>>>(gain, xh, xl);
    kv_post<<<(Bb * Ss * KVHh) / 8, 256>>>(kh, kl, vf);

    flash2<<<dim3(Ss / 64, Hh, Bb), 128, FL2_SMEM>>>(xh, xl, kh, kl, vf, xf);

    cvt_half<<<(n4w + 255) / 256, 256>>>(Wp, wf, n4w);
    gemm_fp16s<<<dim3(Dd / 128, M / 128), 256, GEMM2_SMEM>>>(xf, wf, out, M, Dd, Dd, Dd);
}

// round 17
// speedup vs baseline: 1.8278x; 1.2450x over previous
#include <cuda_runtime.h>
#include <cuda_bf16.h>
#include <cuda_fp16.h>
#include <math.h>
#include <stdint.h>

#define Bb   2
#define Ss   2048
#define Dd   2048
#define Hh   16
#define KVHh 4
#define HDd  128
#define NQKV 3072      // col layout in g_qkv: 0-2047 q, 2048-2559 k, 2560-3071 v

typedef __nv_bfloat16 bf16;

// ---------------- scratch (static device globals; no allocs) ----------------
__device__ float g_qkv[Bb * Ss * NQKV];
__device__ float g_cos[Ss * 64];
__device__ float g_sin[Ss * 64];
// fp16 2-term split of x; later overwritten by q-split (q_post) then attn-out (flash)
__device__ __align__(16) __half g_xfh[Bb * Ss * Dd];
__device__ __align__(16) __half g_xfl[Bb * Ss * Dd];
// fp16 weights: fused [Wq;Wk;Wv] (3072x2048), later reused for Wp (2048x2048)
__device__ __align__(16) __half g_wf16[NQKV * Dd];
// fp16 K (rms+rope) and V
__device__ __align__(16) __half g_kf[Bb * Ss * KVHh * HDd];
__device__ __align__(16) __half g_vf[Bb * Ss * KVHh * HDd];

// ---------------- helpers ----------------------------------------------------
__device__ __forceinline__ uint32_t smem_u32(const void* p) {
    uint32_t a;
    asm("{ .reg .u64 t; cvta.to.shared.u64 t, %1; cvt.u32.u64 %0, t; }" : "=r"(a) : "l"(p));
    return a;
}
#define CP_ASYNC16(dst, src) \
    asm volatile("cp.async.cg.shared.global [%0], [%1], 16;" :: "r"(dst), "l"(src) : "memory")
#define CP_COMMIT()  asm volatile("cp.async.commit_group;" ::: "memory")
#define CP_WAIT1()   asm volatile("cp.async.wait_group 1;" ::: "memory")
#define CP_WAIT0()   asm volatile("cp.async.wait_group 0;" ::: "memory")

__device__ __forceinline__ void mma16816h(float* d, const uint32_t* a, const uint32_t* b) {
    asm volatile("mma.sync.aligned.m16n8k16.row.col.f32.f16.f16.f32 "
        "{%0,%1,%2,%3}, {%4,%5,%6,%7}, {%8,%9}, {%0,%1,%2,%3};"
        : "+f"(d[0]), "+f"(d[1]), "+f"(d[2]), "+f"(d[3])
        : "r"(a[0]), "r"(a[1]), "r"(a[2]), "r"(a[3]), "r"(b[0]), "r"(b[1]));
}
#define LDSM4T(r, a) \
    asm volatile("ldmatrix.sync.aligned.m8n8.x4.trans.shared.b16 {%0,%1,%2,%3}, [%4];" \
        : "=r"((r)[0]), "=r"((r)[1]), "=r"((r)[2]), "=r"((r)[3]) : "r"(a))

// pack two fp32 into fp16x2 (hi) and residuals into fp16x2 (lo)
__device__ __forceinline__ void splitpkh(float x0, float x1, uint32_t& hi, uint32_t& lo) {
    __half h0 = __float2half_rn(x0), h1 = __float2half_rn(x1);
    __half2 th = __halves2half2(h0, h1);
    hi = *(uint32_t*)&th;
    __half r0 = __float2half_rn(x0 - __half2float(h0));
    __half r1 = __float2half_rn(x1 - __half2float(h1));
    __half2 tl = __halves2half2(r0, r1);
    lo = *(uint32_t*)&tl;
}
__device__ __forceinline__ uint32_t packh2(float x0, float x1) {
    __half2 h = __floats2half2_rn(x0, x1);
    return *(uint32_t*)&h;
}

// ---------------- RoPE table ------------------------------------------------
__global__ void rope_table_kernel() {
    int i = blockIdx.x * blockDim.x + threadIdx.x;
    if (i >= Ss * 64) return;
    int s = i >> 6, j = i & 63;
    float e   = (float)(2 * j) / (float)HDd;
    float inv = 1.0f / powf(10000.0f, e);
    float ang = (float)s * inv;
    g_cos[i] = (float)cos((double)ang);
    g_sin[i] = (float)sin((double)ang);
}

// ---------------- fp32 -> fp16 hi/lo split ----------------------------------
__global__ __launch_bounds__(256) void cvt_splith(const float* __restrict__ src,
                                                  __half* __restrict__ hi,
                                                  __half* __restrict__ lo, int n4) {
    int i = blockIdx.x * blockDim.x + threadIdx.x;
    if (i >= n4) return;
    float4 v = ((const float4*)src)[i];
    uint32_t h0, l0, h1, l1;
    splitpkh(v.x, v.y, h0, l0);
    splitpkh(v.z, v.w, h1, l1);
    ((uint32_t*)hi)[2 * i] = h0; ((uint32_t*)hi)[2 * i + 1] = h1;
    ((uint32_t*)lo)[2 * i] = l0; ((uint32_t*)lo)[2 * i + 1] = l1;
}

// ---------------- fp32 -> fp16 ----------------------------------------------
__global__ __launch_bounds__(256) void cvt_half(const float* __restrict__ src,
                                                __half* __restrict__ dst, int n4) {
    int i = blockIdx.x * blockDim.x + threadIdx.x;
    if (i >= n4) return;
    float4 v = ((const float4*)src)[i];
    ((__half2*)dst)[2 * i]     = __floats2half2_rn(v.x, v.y);
    ((__half2*)dst)[2 * i + 1] = __floats2half2_rn(v.z, v.w);
}

// ---------------- 2-term fp16 HMMA GEMM: C = (Ah+Al) @ B^T -------------------
// A hi/lo fp16 [M,K]; B plain fp16 [N,K]. CTA 128x128, K-chunk 32, 8 warps.
#define LDA        40
#define ARRB       (128 * LDA * 2)          // 10240 B per operand array
#define STAGE3     (3 * ARRB)               // Ah, Al, B
#define GEMM3_SMEM (2 * STAGE3)             // 61440 B

__device__ __forceinline__ void gemm2t_load(
    uint32_t sm32, int buf, int tid, int c,
    const __half* __restrict__ Ah, const __half* __restrict__ Al,
    const __half* __restrict__ B, int bm, int bn, int K) {
    int row = tid >> 2;
    int t16 = tid & 3;
    uint32_t so = sm32 + buf * STAGE3 + (uint32_t)row * 80 + (uint32_t)t16 * 16;
    size_t gA = (size_t)(bm + row) * K + (size_t)c * 32 + t16 * 8;
    size_t gB = (size_t)(bn + row) * K + (size_t)c * 32 + t16 * 8;
    size_t stp = (size_t)64 * K;
    CP_ASYNC16(so,                       Ah + gA);
    CP_ASYNC16(so + 64 * 80,             Ah + gA + stp);
    CP_ASYNC16(so + ARRB,                Al + gA);
    CP_ASYNC16(so + ARRB + 64 * 80,      Al + gA + stp);
    CP_ASYNC16(so + 2 * ARRB,            B + gB);
    CP_ASYNC16(so + 2 * ARRB + 64 * 80,  B + gB + stp);
}

__global__ __launch_bounds__(256) void gemm_fp16_2t(
    const __half* __restrict__ Ah, const __half* __restrict__ Al,
    const __half* __restrict__ B,
    float* __restrict__ C, int M, int N, int K, int ldc) {
    extern __shared__ char sm[];
    const uint32_t sm32 = smem_u32(sm);
    const int tid  = threadIdx.x;
    const int wid  = tid >> 5, lane = tid & 31;
    const int lr   = lane >> 2, lc = lane & 3;
    const int wm   = wid & 1;
    const int wn   = wid >> 1;
    const int bm = blockIdx.y * 128, bn = blockIdx.x * 128;

    float acc[4][4][4];
#pragma unroll
    for (int i = 0; i < 4; i++)
#pragma unroll
        for (int j = 0; j < 4; j++)
#pragma unroll
            for (int r = 0; r < 4; r++) acc[i][j][r] = 0.0f;

    const int NC = K >> 5;
    gemm2t_load(sm32, 0, tid, 0, Ah, Al, B, bm, bn, K);
    CP_COMMIT();

    for (int c = 0; c < NC; c++) {
        const int buf = c & 1;
        if (c + 1 < NC) {
            gemm2t_load(sm32, buf ^ 1, tid, c + 1, Ah, Al, B, bm, bn, K);
            CP_COMMIT();
            CP_WAIT1();
        } else {
            CP_WAIT0();
        }
        __syncthreads();

        const __half* sA  = (const __half*)(sm + buf * STAGE3);
        const __half* sAl = sA + 128 * LDA;
        const __half* sB  = sA + 2 * 128 * LDA;
#pragma unroll
        for (int kst = 0; kst < 2; kst++) {
            const int pp = kst * 8 + lc;
            uint32_t ah[4][4], al[4][4], bh[4][2];
#pragma unroll
            for (int mt = 0; mt < 4; mt++) {
                int r0 = wm * 64 + mt * 16 + lr;
                ah[mt][0] = *(const uint32_t*)(sA + r0 * LDA + pp * 2);
                ah[mt][1] = *(const uint32_t*)(sA + (r0 + 8) * LDA + pp * 2);
                ah[mt][2] = *(const uint32_t*)(sA + r0 * LDA + (pp + 4) * 2);
                ah[mt][3] = *(const uint32_t*)(sA + (r0 + 8) * LDA + (pp + 4) * 2);
                al[mt][0] = *(const uint32_t*)(sAl + r0 * LDA + pp * 2);
                al[mt][1] = *(const uint32_t*)(sAl + (r0 + 8) * LDA + pp * 2);
                al[mt][2] = *(const uint32_t*)(sAl + r0 * LDA + (pp + 4) * 2);
                al[mt][3] = *(const uint32_t*)(sAl + (r0 + 8) * LDA + (pp + 4) * 2);
            }
#pragma unroll
            for (int nt = 0; nt < 4; nt++) {
                int n0 = wn * 32 + nt * 8 + lr;
                bh[nt][0] = *(const uint32_t*)(sB + n0 * LDA + pp * 2);
                bh[nt][1] = *(const uint32_t*)(sB + n0 * LDA + (pp + 4) * 2);
            }
#pragma unroll
            for (int mt = 0; mt < 4; mt++)
#pragma unroll
                for (int nt = 0; nt < 4; nt++)
                    mma16816h(acc[mt][nt], ah[mt], bh[nt]);
#pragma unroll
            for (int mt = 0; mt < 4; mt++)
#pragma unroll
                for (int nt = 0; nt < 4; nt++)
                    mma16816h(acc[mt][nt], al[mt], bh[nt]);
        }
        __syncthreads();
    }

#pragma unroll
    for (int mt = 0; mt < 4; mt++) {
        int m = bm + wm * 64 + mt * 16 + lr;
#pragma unroll
        for (int nt = 0; nt < 4; nt++) {
            int n = bn + wn * 32 + nt * 8 + lc * 2;
            *(float2*)(C + (size_t)m * ldc + n)       = make_float2(acc[mt][nt][0], acc[mt][nt][1]);
            *(float2*)(C + (size_t)(m + 8) * ldc + n) = make_float2(acc[mt][nt][2], acc[mt][nt][3]);
        }
    }
}

// ---------------- plain fp16 HMMA GEMM (1-term, out-proj) -------------------
#define STAGE2      (2 * ARRB)
#define GEMM2_SMEM  (2 * STAGE2)

__device__ __forceinline__ void gemm16_load(
    uint32_t sm32, int buf, int tid, int c,
    const __half* __restrict__ A, const __half* __restrict__ B,
    int bm, int bn, int K) {
    int row = tid >> 2;
    int t16 = tid & 3;
    uint32_t so = sm32 + buf * STAGE2 + (uint32_t)row * 80 + (uint32_t)t16 * 16;
    size_t gA = (size_t)(bm + row) * K + (size_t)c * 32 + t16 * 8;
    size_t gB = (size_t)(bn + row) * K + (size_t)c * 32 + t16 * 8;
    size_t stp = (size_t)64 * K;
    CP_ASYNC16(so,                   A + gA);
    CP_ASYNC16(so + 64 * 80,         A + gA + stp);
    CP_ASYNC16(so + ARRB,            B + gB);
    CP_ASYNC16(so + ARRB + 64 * 80,  B + gB + stp);
}

__global__ __launch_bounds__(256) void gemm_fp16s(
    const __half* __restrict__ A, const __half* __restrict__ B,
    float* __restrict__ C, int M, int N, int K, int ldc) {
    extern __shared__ char sm[];
    const uint32_t sm32 = smem_u32(sm);
    const int tid  = threadIdx.x;
    const int wid  = tid >> 5, lane = tid & 31;
    const int lr   = lane >> 2, lc = lane & 3;
    const int wm   = wid & 1;
    const int wn   = wid >> 1;
    const int bm = blockIdx.y * 128, bn = blockIdx.x * 128;

    float acc[4][4][4];
#pragma unroll
    for (int i = 0; i < 4; i++)
#pragma unroll
        for (int j = 0; j < 4; j++)
#pragma unroll
            for (int r = 0; r < 4; r++) acc[i][j][r] = 0.0f;

    const int NC = K >> 5;
    gemm16_load(sm32, 0, tid, 0, A, B, bm, bn, K);
    CP_COMMIT();

    for (int c = 0; c < NC; c++) {
        const int buf = c & 1;
        if (c + 1 < NC) {
            gemm16_load(sm32, buf ^ 1, tid, c + 1, A, B, bm, bn, K);
            CP_COMMIT();
            CP_WAIT1();
        } else {
            CP_WAIT0();
        }
        __syncthreads();

        const __half* sA = (const __half*)(sm + buf * STAGE2);
        const __half* sB = sA + 128 * LDA;
#pragma unroll
        for (int kst = 0; kst < 2; kst++) {
            const int pp = kst * 8 + lc;
            uint32_t ah[4][4], bh[4][2];
#pragma unroll
            for (int mt = 0; mt < 4; mt++) {
                int r0 = wm * 64 + mt * 16 + lr;
                ah[mt][0] = *(const uint32_t*)(sA + r0 * LDA + pp * 2);
                ah[mt][1] = *(const uint32_t*)(sA + (r0 + 8) * LDA + pp * 2);
                ah[mt][2] = *(const uint32_t*)(sA + r0 * LDA + (pp + 4) * 2);
                ah[mt][3] = *(const uint32_t*)(sA + (r0 + 8) * LDA + (pp + 4) * 2);
            }
#pragma unroll
            for (int nt = 0; nt < 4; nt++) {
                int n0 = wn * 32 + nt * 8 + lr;
                bh[nt][0] = *(const uint32_t*)(sB + n0 * LDA + pp * 2);
                bh[nt][1] = *(const uint32_t*)(sB + n0 * LDA + (pp + 4) * 2);
            }
#pragma unroll
            for (int mt = 0; mt < 4; mt++)
#pragma unroll
                for (int nt = 0; nt < 4; nt++)
                    mma16816h(acc[mt][nt], ah[mt], bh[nt]);
        }
        __syncthreads();
    }

#pragma unroll
    for (int mt = 0; mt < 4; mt++) {
        int m = bm + wm * 64 + mt * 16 + lr;
#pragma unroll
        for (int nt = 0; nt < 4; nt++) {
            int n = bn + wn * 32 + nt * 8 + lc * 2;
            *(float2*)(C + (size_t)m * ldc + n)       = make_float2(acc[mt][nt][0], acc[mt][nt][1]);
            *(float2*)(C + (size_t)(m + 8) * ldc + n) = make_float2(acc[mt][nt][2], acc[mt][nt][3]);
        }
    }
}

// ---------------- q/kv epilogues --------------------------------------------
// q: RMSNorm + RoPE + gain/sqrt(HD) -> fp16 hi/lo split (overwrites x split)
__global__ __launch_bounds__(256) void q_post(const float* __restrict__ gain,
                                              __half* __restrict__ qh, __half* __restrict__ ql) {
    int wid  = blockIdx.x * 8 + (threadIdx.x >> 5);
    int lane = threadIdx.x & 31;
    int h = wid & (Hh - 1);
    int row = wid >> 4;
    int s = row & (Ss - 1);
    const float* base = g_qkv + (size_t)row * NQKV + h * HDd;
    float e0 = base[lane], e1 = base[lane + 32], e2 = base[lane + 64], e3 = base[lane + 96];
    float ssum = e0 * e0 + e1 * e1 + e2 * e2 + e3 * e3;
#pragma unroll
    for (int o = 16; o > 0; o >>= 1) ssum += __shfl_xor_sync(0xffffffffu, ssum, o);
    float r = rsqrtf(ssum * (1.0f / 128.0f) + 1e-6f);
    float g = gain[h] * r * 0.08838834764831845f;
    float c0 = g_cos[s * 64 + lane],      sn0 = g_sin[s * 64 + lane];
    float c1 = g_cos[s * 64 + lane + 32], sn1 = g_sin[s * 64 + lane + 32];
    float o0 = ( e0 * c0  + e2 * sn0) * g;
    float o1 = ( e1 * c1  + e3 * sn1) * g;
    float o2 = (-e0 * sn0 + e2 * c0 ) * g;
    float o3 = (-e1 * sn1 + e3 * c1 ) * g;
    size_t off = (size_t)wid * 128;
    __half h0 = __float2half_rn(o0); qh[off + lane]      = h0; ql[off + lane]      = __float2half_rn(o0 - __half2float(h0));
    __half h1 = __float2half_rn(o1); qh[off + lane + 32] = h1; ql[off + lane + 32] = __float2half_rn(o1 - __half2float(h1));
    __half h2 = __float2half_rn(o2); qh[off + lane + 64] = h2; ql[off + lane + 64] = __float2half_rn(o2 - __half2float(h2));
    __half h3 = __float2half_rn(o3); qh[off + lane + 96] = h3; ql[off + lane + 96] = __float2half_rn(o3 - __half2float(h3));
}

// k: RMSNorm + RoPE -> plain fp16; v: plain fp16
__global__ __launch_bounds__(256) void kv_post(__half* __restrict__ kf, __half* __restrict__ vf) {
    int wid  = blockIdx.x * 8 + (threadIdx.x >> 5);
    int lane = threadIdx.x & 31;
    int kvh = wid & 3;
    int row = wid >> 2;
    int s = row & (Ss - 1);
    const float* kb = g_qkv + (size_t)row * NQKV + 2048 + kvh * HDd;
    const float* vb = kb + 512;
    float e0 = kb[lane], e1 = kb[lane + 32], e2 = kb[lane + 64], e3 = kb[lane + 96];
    float ssum = e0 * e0 + e1 * e1 + e2 * e2 + e3 * e3;
#pragma unroll
    for (int o = 16; o > 0; o >>= 1) ssum += __shfl_xor_sync(0xffffffffu, ssum, o);
    float r = rsqrtf(ssum * (1.0f / 128.0f) + 1e-6f);
    float c0 = g_cos[s * 64 + lane],      sn0 = g_sin[s * 64 + lane];
    float c1 = g_cos[s * 64 + lane + 32], sn1 = g_sin[s * 64 + lane + 32];
    size_t off = (size_t)wid * 128;
    kf[off + lane]      = __float2half_rn(( e0 * c0  + e2 * sn0) * r);
    kf[off + lane + 32] = __float2half_rn(( e1 * c1  + e3 * sn1) * r);
    kf[off + lane + 64] = __float2half_rn((-e0 * sn0 + e2 * c0 ) * r);
    kf[off + lane + 96] = __float2half_rn((-e1 * sn1 + e3 * c1 ) * r);
#pragma unroll
    for (int j = 0; j < 4; j++)
        vf[off + lane + 32 * j] = __float2half_rn(vb[lane + 32 * j]);
}

// ---------------- HMMA flash attention: S 2-term fp16, PV 1-term fp16 -------
// smem arrays (each 64x136 fp16 = 2*FQE bytes): Qh, Ql resident; per stage Kf, Vf.
#define FST 136
#define FQE (64 * FST)                      // elems per array
#define FL2_SMEM (12 * FQE)                 // 6 arrays * 2*FQE bytes = 104448

__device__ __forceinline__ void fl_load_kv(uint32_t sbase, int tid, int b, int kvh, int k0,
    const __half* __restrict__ Kf, const __half* __restrict__ Vf) {
#pragma unroll
    for (int it = 0; it < 8; it++) {
        int c = tid + it * 128;
        int r = c >> 4, o16 = c & 15;
        uint32_t d = sbase + (uint32_t)r * (FST * 2) + o16 * 16;
        size_t g = ((size_t)((b * Ss + k0 + r) * KVHh + kvh)) * HDd + o16 * 8;
        CP_ASYNC16(d,           Kf + g);
        CP_ASYNC16(d + 2 * FQE, Vf + g);
    }
}

__global__ __launch_bounds__(128) void flash2(
    const __half* __restrict__ Qh, const __half* __restrict__ Ql,
    const __half* __restrict__ Kf, const __half* __restrict__ Vf,
    __half* __restrict__ Of) {
    extern __shared__ __half smh[];
    __half* sQh = smh;
    __half* sQl = smh + FQE;
    const uint32_t sm32 = smem_u32(smh);
    const int tid = threadIdx.x, wid = tid >> 5, lane = tid & 31;
    const int lr = lane >> 2, lc = lane & 3;
    const int qt = (Ss / 64 - 1) - blockIdx.x;
    const int h = blockIdx.y, b = blockIdx.z, kvh = h >> 2;
    const int q0 = qt * 64;
    const int wrow = wid * 16;

#pragma unroll
    for (int it = 0; it < 8; it++) {
        int c = tid + it * 128;
        int r = c >> 4, o = (c & 15) * 8;
        size_t g = (size_t)(b * Ss + q0 + r) * Dd + h * HDd + o;
        *(uint4*)(sQh + r * FST + o) = *(const uint4*)(Qh + g);
        *(uint4*)(sQl + r * FST + o) = *(const uint4*)(Ql + g);
    }
    fl_load_kv(sm32 + 4 * FQE, tid, b, kvh, 0, Kf, Vf);
    CP_COMMIT();

    float m0 = -1e30f, m1 = -1e30f, l0 = 0.0f, l1 = 0.0f;
    float O[16][4];
#pragma unroll
    for (int i = 0; i < 16; i++) { O[i][0] = O[i][1] = O[i][2] = O[i][3] = 0.0f; }

    for (int kt = 0; kt <= qt; kt++) {
        const int stage = kt & 1;
        if (kt < qt) {
            fl_load_kv(sm32 + 4 * FQE + (stage ^ 1) * 4 * FQE, tid, b, kvh, (kt + 1) * 64,
                       Kf, Vf);
            CP_COMMIT();
            CP_WAIT1();
        } else {
            CP_WAIT0();
        }
        __syncthreads();

        const __half* sKf = smh + (2 + 2 * stage) * FQE;
        const uint32_t vf32 = sm32 + (6 + 4 * stage) * FQE;   // bytes

        float S[8][4];
#pragma unroll
        for (int nt = 0; nt < 8; nt++) S[nt][0] = S[nt][1] = S[nt][2] = S[nt][3] = 0.0f;

#pragma unroll
        for (int kst = 0; kst < 8; kst++) {
            const int pp2 = kst * 16 + lc * 2;
            const int r0 = wrow + lr;
            uint32_t qa_h[4], qa_l[4];
            qa_h[0] = *(const uint32_t*)(sQh + r0 * FST + pp2);
            qa_h[1] = *(const uint32_t*)(sQh + (r0 + 8) * FST + pp2);
            qa_h[2] = *(const uint32_t*)(sQh + r0 * FST + pp2 + 8);
            qa_h[3] = *(const uint32_t*)(sQh + (r0 + 8) * FST + pp2 + 8);
            qa_l[0] = *(const uint32_t*)(sQl + r0 * FST + pp2);
            qa_l[1] = *(const uint32_t*)(sQl + (r0 + 8) * FST + pp2);
            qa_l[2] = *(const uint32_t*)(sQl + r0 * FST + pp2 + 8);
            qa_l[3] = *(const uint32_t*)(sQl + (r0 + 8) * FST + pp2 + 8);
#pragma unroll
            for (int nt = 0; nt < 8; nt++) {
                const int n0 = nt * 8 + lr;
                uint32_t kb[2];
                kb[0] = *(const uint32_t*)(sKf + n0 * FST + pp2);
                kb[1] = *(const uint32_t*)(sKf + n0 * FST + pp2 + 8);
                mma16816h(S[nt], qa_h, kb);
                mma16816h(S[nt], qa_l, kb);
            }
        }

        if (kt == qt) {
            const int row0 = q0 + wrow + lr;
#pragma unroll
            for (int nt = 0; nt < 8; nt++) {
                const int col = kt * 64 + nt * 8 + lc * 2;
                if (col     > row0)     S[nt][0] = -1e30f;
                if (col + 1 > row0)     S[nt][1] = -1e30f;
                if (col     > row0 + 8) S[nt][2] = -1e30f;
                if (col + 1 > row0 + 8) S[nt][3] = -1e30f;
            }
        }

        float rm0 = -1e30f, rm1 = -1e30f;
#pragma unroll
        for (int nt = 0; nt < 8; nt++) {
            rm0 = fmaxf(rm0, fmaxf(S[nt][0], S[nt][1]));
            rm1 = fmaxf(rm1, fmaxf(S[nt][2], S[nt][3]));
        }
        rm0 = fmaxf(rm0, __shfl_xor_sync(0xffffffffu, rm0, 1));
        rm0 = fmaxf(rm0, __shfl_xor_sync(0xffffffffu, rm0, 2));
        rm1 = fmaxf(rm1, __shfl_xor_sync(0xffffffffu, rm1, 1));
        rm1 = fmaxf(rm1, __shfl_xor_sync(0xffffffffu, rm1, 2));
        float mn0 = fmaxf(m0, rm0), mn1 = fmaxf(m1, rm1);
        float a0 = __expf(m0 - mn0), a1 = __expf(m1 - mn1);
        float rs0 = 0.0f, rs1 = 0.0f;
#pragma unroll
        for (int nt = 0; nt < 8; nt++) {
            S[nt][0] = __expf(S[nt][0] - mn0);
            S[nt][1] = __expf(S[nt][1] - mn0);
            S[nt][2] = __expf(S[nt][2] - mn1);
            S[nt][3] = __expf(S[nt][3] - mn1);
            rs0 += S[nt][0] + S[nt][1];
            rs1 += S[nt][2] + S[nt][3];
        }
        rs0 += __shfl_xor_sync(0xffffffffu, rs0, 1);
        rs0 += __shfl_xor_sync(0xffffffffu, rs0, 2);
        rs1 += __shfl_xor_sync(0xffffffffu, rs1, 1);
        rs1 += __shfl_xor_sync(0xffffffffu, rs1, 2);
        l0 = l0 * a0 + rs0;
        l1 = l1 * a1 + rs1;
        m0 = mn0; m1 = mn1;
#pragma unroll
        for (int i = 0; i < 16; i++) {
            O[i][0] *= a0; O[i][1] *= a0; O[i][2] *= a1; O[i][3] *= a1;
        }

        // P -> fp16 a-frags
        uint32_t pf[4][4];
#pragma unroll
        for (int ks = 0; ks < 4; ks++) {
            pf[ks][0] = packh2(S[2 * ks][0],     S[2 * ks][1]);
            pf[ks][1] = packh2(S[2 * ks][2],     S[2 * ks][3]);
            pf[ks][2] = packh2(S[2 * ks + 1][0], S[2 * ks + 1][1]);
            pf[ks][3] = packh2(S[2 * ks + 1][2], S[2 * ks + 1][3]);
        }

        // O += P . V  (fp16 1-term)
#pragma unroll
        for (int ks = 0; ks < 4; ks++) {
            const uint32_t va = ((uint32_t)(16 * ks + (lane & 15)) * FST) * 2 + (lane >> 4) * 16;
#pragma unroll
            for (int ntp = 0; ntp < 8; ntp++) {
                uint32_t v4[4];
                LDSM4T(v4, vf32 + va + ntp * 32);
                uint32_t b0[2] = {v4[0], v4[1]}, b1[2] = {v4[2], v4[3]};
                mma16816h(O[2 * ntp],     pf[ks], b0);
                mma16816h(O[2 * ntp + 1], pf[ks], b1);
            }
        }
        __syncthreads();
    }

    float il0 = 1.0f / l0, il1 = 1.0f / l1;
    size_t r0 = (size_t)(b * Ss + q0 + wrow + lr) * Dd + h * HDd;
    size_t r1 = r0 + 8 * (size_t)Dd;
#pragma unroll
    for (int nt = 0; nt < 16; nt++) {
        int cc = nt * 8 + lc * 2;
        *(__half2*)(Of + r0 + cc) = __floats2half2_rn(O[nt][0] * il0, O[nt][1] * il0);
        *(__half2*)(Of + r1 + cc) = __floats2half2_rn(O[nt][2] * il1, O[nt][3] * il1);
    }
}

// ---------------- launch ----------------------------------------------------
extern "C" void kernel_launch(void* const* d_in, const int* in_sizes, int n_in,
                              void* d_out, int out_size) {
    const float* x    = (const float*)d_in[0];
    const float* Wq   = (const float*)d_in[1];
    const float* Wk   = (const float*)d_in[2];
    const float* Wv   = (const float*)d_in[3];
    const float* Wp   = (const float*)d_in[4];
    const float* gain = (const float*)d_in[5];
    float* out = (float*)d_out;

    float* qkv;
    __half *xfh, *xfl, *wf, *kf, *vf;
    cudaGetSymbolAddress((void**)&qkv, g_qkv);
    cudaGetSymbolAddress((void**)&xfh, g_xfh);
    cudaGetSymbolAddress((void**)&xfl, g_xfl);
    cudaGetSymbolAddress((void**)&wf,  g_wf16);
    cudaGetSymbolAddress((void**)&kf,  g_kf);
    cudaGetSymbolAddress((void**)&vf,  g_vf);

    cudaFuncSetAttribute(gemm_fp16_2t, cudaFuncAttributeMaxDynamicSharedMemorySize, GEMM3_SMEM);
    cudaFuncSetAttribute(gemm_fp16s,   cudaFuncAttributeMaxDynamicSharedMemorySize, GEMM2_SMEM);
    cudaFuncSetAttribute(flash2,       cudaFuncAttributeMaxDynamicSharedMemorySize, FL2_SMEM);

    const int M = Bb * Ss;                 // 4096
    const int n4x = M * Dd / 4;
    const int n4w = Dd * Dd / 4;
    const int n4k = 512 * Dd / 4;

    rope_table_kernel<<<(Ss * 64 + 255) / 256, 256>>>();

    // x -> fp16 hi/lo split
    cvt_splith<<<(n4x + 255) / 256, 256>>>(x, xfh, xfl, n4x);

    // fused fp16 weights: rows 0-2047 Wq, 2048-2559 Wk, 2560-3071 Wv
    cvt_half<<<(n4w + 255) / 256, 256>>>(Wq, wf, n4w);
    cvt_half<<<(n4k + 255) / 256, 256>>>(Wk, wf + (size_t)2048 * Dd, n4k);
    cvt_half<<<(n4k + 255) / 256, 256>>>(Wv, wf + (size_t)2560 * Dd, n4k);

    // fused QKV projection: 2-term fp16
    gemm_fp16_2t<<<dim3(NQKV / 128, M / 128), 256, GEMM3_SMEM>>>(
        xfh, xfl, wf, qkv, M, NQKV, Dd, NQKV);

    // posts: q split overwrites xfh/xfl; k/v to fp16 buffers
    q_post<<<(Bb * Ss * Hh) / 8, 256>>>(gain, xfh, xfl);
    kv_post<<<(Bb * Ss * KVHh) / 8, 256>>>(kf, vf);

    // flash: Q split from xfh/xfl; writes fp16 attn-out into xfh
    flash2<<<dim3(Ss / 64, Hh, Bb), 128, FL2_SMEM>>>(xfh, xfl, kf, vf, xfh);

    // out-proj: 1-term fp16
    cvt_half<<<(n4w + 255) / 256, 256>>>(Wp, wf, n4w);
    gemm_fp16s<<<dim3(Dd / 128, M / 128), 256, GEMM2_SMEM>>>(xfh, wf, out, M, Dd, Dd, Dd);
}